// round 1
// baseline (speedup 1.0000x reference)
#include <cuda_runtime.h>
#include <math.h>

#define NN 16384
#define EE 65536
#define DD 64
#define GG 512
#define BN_EPS 1e-5f

// ---------------- scratch (no allocations allowed) ----------------
__device__ float g_h[NN * DD];          // node features / GRU hidden (4 MB)
__device__ float g_ef[EE * DD];         // edge MLP1 output (16 MB)
__device__ float g_aggr[NN * DD];       // scatter-add target (4 MB)
__device__ float g_Wr[2 * DD * DD * DD];// permuted mlp2 weights, [l][(i*64+c)][o] (2 MB)
__device__ float g_pooled[GG * DD];     // global_add_pool (128 KB)

// ---------------- tiny utility kernels ----------------
__global__ void k_zero_aggr() {
    int i = blockIdx.x * blockDim.x + threadIdx.x;
    g_aggr[i] = 0.f;
}
__global__ void k_zero_pooled() {
    int i = blockIdx.x * blockDim.x + threadIdx.x;
    g_pooled[i] = 0.f;
}

// Permute mlp2_w [l][(i*64+o)][c] -> g_Wr [l][(i*64+c)][o]
__global__ void k_perm(const float* __restrict__ m2) {
    int idx = blockIdx.x * blockDim.x + threadIdx.x;   // 2*4096*64
    int l = idx >> 18;
    int rem = idx & 262143;
    int k = rem >> 6, o = rem & 63;
    int i = k >> 6, c = k & 63;
    g_Wr[idx] = m2[l * 262144 + ((i << 6) + o) * 64 + c];
}

// out = relu(x @ lin0_w.T + b), x:[N,16], w:[64,16]
__global__ void k_lin0(const float* __restrict__ x, const float* __restrict__ w,
                       const float* __restrict__ b) {
    int idx = blockIdx.x * blockDim.x + threadIdx.x;   // N*64
    int n = idx >> 6, o = idx & 63;
    float a = b[o];
#pragma unroll
    for (int f = 0; f < 16; f++) a += x[n * 16 + f] * w[o * 16 + f];
    g_h[idx] = fmaxf(a, 0.f);
}

// ef = relu(edge_attr @ mlp1_w.T + b), ea:[E,6], w:[64,6]
__global__ void k_emlp(const float* __restrict__ ea, const float* __restrict__ w,
                       const float* __restrict__ b) {
    int idx = blockIdx.x * blockDim.x + threadIdx.x;   // E*64
    int e = idx >> 6, c = idx & 63;
    float a = b[c];
#pragma unroll
    for (int k = 0; k < 6; k++) a += ea[e * 6 + k] * w[c * 6 + k];
    g_ef[idx] = fmaxf(a, 0.f);
}

// ---------------- the big one: fused NNConv message + scatter ----------------
// msg[e,o] = sum_{i,c} u[e,i]*v[e,c]*Wr[(i*64+c),o] + sum_i u[e,i]*b2[i*64+o]
// Tile: 64 edges x 64 outputs, K=4096 in 64 chunks (chunk = fixed i).
// A generated on the fly: A[m][kk] = Us[m][ich] * Vs_T[kk][m].
__global__ void k_msg(int l, const float* __restrict__ b2, const int* __restrict__ ei) {
    __shared__ float Us[64 * 64];   // [m][i]   (natural)
    __shared__ float Vs[64 * 64];   // [c][m]   (transposed)
    __shared__ float Bs[64 * 64];   // [k][o]
    const float* Wr = g_Wr + l * 262144;

    const int t = threadIdx.x;          // 0..255
    const int e0 = blockIdx.x * 64;

    // Load Us: i-fast (coalesced gather of h rows), write [m][i] conflict-free.
#pragma unroll
    for (int p = 0; p < 16; p++) {
        int idx = t + p * 256;
        int m = idx >> 6, i = idx & 63;
        int s = ei[e0 + m];
        Us[m * 64 + i] = g_h[s * 64 + i];
    }
    // Load Vs transposed: m-fast (conflict-free smem write; strided global read
    // re-hits L1 since each thread stays in one ef row).
#pragma unroll
    for (int p = 0; p < 16; p++) {
        int idx = t + p * 256;
        int m = idx & 63, c = idx >> 6;
        Vs[c * 64 + m] = g_ef[(e0 + m) * 64 + c];
    }

    const int tx = t & 15, ty = t >> 4;
    const int m0 = ty * 4, n0 = tx * 4;
    float acc[4][4];
#pragma unroll
    for (int a = 0; a < 4; a++)
#pragma unroll
        for (int b = 0; b < 4; b++) acc[a][b] = 0.f;

    for (int ich = 0; ich < 64; ich++) {
        __syncthreads();
#pragma unroll
        for (int p = 0; p < 4; p++) {
            int i4 = t + p * 256;
            ((float4*)Bs)[i4] = ((const float4*)(Wr + ich * 4096))[i4];
        }
        __syncthreads();
        float a0 = Us[(m0 + 0) * 64 + ich];
        float a1 = Us[(m0 + 1) * 64 + ich];
        float a2 = Us[(m0 + 2) * 64 + ich];
        float a3 = Us[(m0 + 3) * 64 + ich];
#pragma unroll
        for (int kk = 0; kk < 64; kk++) {
            float4 v4 = *(float4*)&Vs[kk * 64 + m0];
            float4 b4 = *(float4*)&Bs[kk * 64 + n0];
            float av0 = a0 * v4.x, av1 = a1 * v4.y, av2 = a2 * v4.z, av3 = a3 * v4.w;
            acc[0][0] += av0 * b4.x; acc[0][1] += av0 * b4.y; acc[0][2] += av0 * b4.z; acc[0][3] += av0 * b4.w;
            acc[1][0] += av1 * b4.x; acc[1][1] += av1 * b4.y; acc[1][2] += av1 * b4.z; acc[1][3] += av1 * b4.w;
            acc[2][0] += av2 * b4.x; acc[2][1] += av2 * b4.y; acc[2][2] += av2 * b4.z; acc[2][3] += av2 * b4.w;
            acc[3][0] += av3 * b4.x; acc[3][1] += av3 * b4.y; acc[3][2] += av3 * b4.z; acc[3][3] += av3 * b4.w;
        }
    }

    // Bias term: acc[mi][ni] += sum_i u[m][i] * b2[i*64 + n]
    __syncthreads();
#pragma unroll
    for (int p = 0; p < 4; p++) {
        int i4 = t + p * 256;
        ((float4*)Bs)[i4] = ((const float4*)b2)[i4];
    }
    __syncthreads();
#pragma unroll
    for (int kk = 0; kk < 64; kk++) {
        float u0 = Us[(m0 + 0) * 64 + kk];
        float u1 = Us[(m0 + 1) * 64 + kk];
        float u2 = Us[(m0 + 2) * 64 + kk];
        float u3 = Us[(m0 + 3) * 64 + kk];
        float4 b4 = *(float4*)&Bs[kk * 64 + n0];
        acc[0][0] += u0 * b4.x; acc[0][1] += u0 * b4.y; acc[0][2] += u0 * b4.z; acc[0][3] += u0 * b4.w;
        acc[1][0] += u1 * b4.x; acc[1][1] += u1 * b4.y; acc[1][2] += u1 * b4.z; acc[1][3] += u1 * b4.w;
        acc[2][0] += u2 * b4.x; acc[2][1] += u2 * b4.y; acc[2][2] += u2 * b4.z; acc[2][3] += u2 * b4.w;
        acc[3][0] += u3 * b4.x; acc[3][1] += u3 * b4.y; acc[3][2] += u3 * b4.z; acc[3][3] += u3 * b4.w;
    }

    // Fused scatter-add (segment_sum over dst)
#pragma unroll
    for (int mi = 0; mi < 4; mi++) {
        int e = e0 + m0 + mi;
        int d = ei[EE + e];
        float* ap = g_aggr + d * 64 + n0;
        atomicAdd(ap + 0, acc[mi][0]);
        atomicAdd(ap + 1, acc[mi][1]);
        atomicAdd(ap + 2, acc[mi][2]);
        atomicAdd(ap + 3, acc[mi][3]);
    }
}

// ---------------- per-node: root + bias + relu + BN + GRU step ----------------
__global__ void k_node(const float* __restrict__ root_w, const float* __restrict__ conv_b,
                       const float* __restrict__ bn, const float* __restrict__ wih,
                       const float* __restrict__ whh, const float* __restrict__ bih,
                       const float* __restrict__ bhh) {
    __shared__ float hrow[64], mrow[64];
    int n = blockIdx.x, o = threadIdx.x;
    float hv = g_h[n * 64 + o];
    hrow[o] = hv;
    __syncthreads();
    float acc = g_aggr[n * 64 + o] + conv_b[o];
#pragma unroll 16
    for (int i = 0; i < 64; i++) acc += hrow[i] * root_w[i * 64 + o];
    acc = fmaxf(acc, 0.f);
    acc = (acc - bn[128 + o]) * rsqrtf(bn[192 + o] + BN_EPS) * bn[o] + bn[64 + o];
    mrow[o] = acc;
    __syncthreads();
    float gir = bih[o], giz = bih[64 + o], gin = bih[128 + o];
    float ghr = bhh[o], ghz = bhh[64 + o], ghn = bhh[128 + o];
#pragma unroll 8
    for (int i = 0; i < 64; i++) {
        float mi = mrow[i], hi = hrow[i];
        gir += mi * wih[o * 64 + i];
        giz += mi * wih[(64 + o) * 64 + i];
        gin += mi * wih[(128 + o) * 64 + i];
        ghr += hi * whh[o * 64 + i];
        ghz += hi * whh[(64 + o) * 64 + i];
        ghn += hi * whh[(128 + o) * 64 + i];
    }
    float r = 1.f / (1.f + expf(-(gir + ghr)));
    float z = 1.f / (1.f + expf(-(giz + ghz)));
    float nv = tanhf(gin + r * ghn);
    g_h[n * 64 + o] = (1.f - z) * nv + z * hv;
}

// ---------------- GraphConv scatter: aggr[dst] += h[src] ----------------
__global__ void k_gcsc(const int* __restrict__ ei) {
    int idx = blockIdx.x * blockDim.x + threadIdx.x;   // E*64
    int e = idx >> 6, o = idx & 63;
    int s = ei[e], d = ei[EE + e];
    atomicAdd(&g_aggr[d * 64 + o], g_h[s * 64 + o]);
}

// ---------------- GraphConv linear + BN + pool scatter ----------------
__global__ void k_gconv(const float* __restrict__ relw, const float* __restrict__ relb,
                        const float* __restrict__ rootw, const float* __restrict__ bnl,
                        const int* __restrict__ batch) {
    __shared__ float arow[64], hrow[64];
    int n = blockIdx.x, o = threadIdx.x;
    arow[o] = g_aggr[n * 64 + o];
    hrow[o] = g_h[n * 64 + o];
    __syncthreads();
    float a = relb[o];
#pragma unroll 16
    for (int i = 0; i < 64; i++)
        a += arow[i] * relw[o * 64 + i] + hrow[i] * rootw[o * 64 + i];
    a = fmaxf(a, 0.f);
    a = (a - bnl[128 + o]) * rsqrtf(bnl[192 + o] + BN_EPS) * bnl[o] + bnl[64 + o];
    atomicAdd(&g_pooled[batch[n] * 64 + o], a);
}

// ---------------- FC head: one block per graph ----------------
__global__ void k_head(const float* __restrict__ fc1_w, const float* __restrict__ fc1_b,
                       const float* __restrict__ fcbn1, const float* __restrict__ fc2_w,
                       const float* __restrict__ fc2_b, const float* __restrict__ fcbn2,
                       const float* __restrict__ fcl_w, const float* __restrict__ fcl_b,
                       float* __restrict__ out) {
    __shared__ float prow[64], f1[256], f2[128], red[256];
    int g = blockIdx.x, t = threadIdx.x;
    if (t < 64) prow[t] = g_pooled[g * 64 + t];
    __syncthreads();
    {
        float a = fc1_b[t];
#pragma unroll 16
        for (int i = 0; i < 64; i++) a += prow[i] * fc1_w[t * 64 + i];
        a = fmaxf(a, 0.f);
        a = (a - fcbn1[512 + t]) * rsqrtf(fcbn1[768 + t] + BN_EPS) * fcbn1[t] + fcbn1[256 + t];
        f1[t] = a;
    }
    __syncthreads();
    if (t < 128) {
        float a = fc2_b[t];
#pragma unroll 16
        for (int i = 0; i < 256; i++) a += f1[i] * fc2_w[t * 256 + i];
        a = fmaxf(a, 0.f);
        a = (a - fcbn2[256 + t]) * rsqrtf(fcbn2[384 + t] + BN_EPS) * fcbn2[t] + fcbn2[128 + t];
        f2[t] = a;
    }
    __syncthreads();
    red[t] = (t < 128) ? f2[t] * fcl_w[t] : 0.f;
    __syncthreads();
    for (int s = 128; s > 0; s >>= 1) {
        if (t < s) red[t] += red[t + s];
        __syncthreads();
    }
    if (t == 0) out[g] = red[0] + fcl_b[0];
}

// ---------------- launcher ----------------
extern "C" void kernel_launch(void* const* d_in, const int* in_sizes, int n_in,
                              void* d_out, int out_size) {
    const float* x        = (const float*)d_in[0];
    const float* edge_attr= (const float*)d_in[1];
    const float* lin0_w   = (const float*)d_in[2];
    const float* lin0_b   = (const float*)d_in[3];
    const float* mlp1_w   = (const float*)d_in[4];
    const float* mlp1_b   = (const float*)d_in[5];
    const float* mlp2_w   = (const float*)d_in[6];
    const float* mlp2_b   = (const float*)d_in[7];
    const float* root_w   = (const float*)d_in[8];
    const float* conv_b   = (const float*)d_in[9];
    const float* bn       = (const float*)d_in[10];
    const float* gru_wih  = (const float*)d_in[11];
    const float* gru_whh  = (const float*)d_in[12];
    const float* gru_bih  = (const float*)d_in[13];
    const float* gru_bhh  = (const float*)d_in[14];
    const float* gc_rel_w = (const float*)d_in[15];
    const float* gc_rel_b = (const float*)d_in[16];
    const float* gc_root_w= (const float*)d_in[17];
    const float* bnl      = (const float*)d_in[18];
    const float* fc1_w    = (const float*)d_in[19];
    const float* fc1_b    = (const float*)d_in[20];
    const float* fcbn1    = (const float*)d_in[21];
    const float* fc2_w    = (const float*)d_in[22];
    const float* fc2_b    = (const float*)d_in[23];
    const float* fcbn2    = (const float*)d_in[24];
    const float* fcl_w    = (const float*)d_in[25];
    const float* fcl_b    = (const float*)d_in[26];
    const int*   ei       = (const int*)d_in[27];
    const int*   batch    = (const int*)d_in[28];
    float* out = (float*)d_out;

    k_perm<<<2048, 256>>>(mlp2_w);
    k_lin0<<<(NN * DD) / 256, 256>>>(x, lin0_w, lin0_b);

    for (int l = 0; l < 2; l++) {
        k_emlp<<<(EE * DD) / 256, 256>>>(edge_attr, mlp1_w + l * 64 * 6, mlp1_b + l * 64);
        k_zero_aggr<<<(NN * DD) / 256, 256>>>();
        k_msg<<<EE / 64, 256>>>(l, mlp2_b + l * 4096, ei);
        k_node<<<NN, 64>>>(root_w + l * 4096, conv_b + l * 64, bn + l * 256,
                           gru_wih + l * 192 * 64, gru_whh + l * 192 * 64,
                           gru_bih + l * 192, gru_bhh + l * 192);
    }

    k_zero_aggr<<<(NN * DD) / 256, 256>>>();
    k_gcsc<<<(EE * DD) / 256, 256>>>(ei);
    k_zero_pooled<<<(GG * DD) / 256, 256>>>();
    k_gconv<<<NN, 64>>>(gc_rel_w, gc_rel_b, gc_root_w, bnl, batch);
    k_head<<<GG, 256>>>(fc1_w, fc1_b, fcbn1, fc2_w, fc2_b, fcbn2, fcl_w, fcl_b, out);
}

// round 9
// speedup vs baseline: 1.0345x; 1.0345x over previous
#include <cuda_runtime.h>
#include <math.h>
#include <stdint.h>

#define NN 16384
#define EE 65536
#define DD 64
#define GG 512
#define BN_EPS 1e-5f
#define NCH 65           // 64 uv-chunks + 1 bias chunk
#define MT 64            // edges per block in mma kernel

// ---------------- scratch (no allocations allowed) ----------------
__device__ float g_h[NN * DD];           // node features / GRU hidden
__device__ float g_ef[EE * DD];          // edge MLP1 output
__device__ float g_aggr[NN * DD];        // scatter-add target
__device__ float g_pooled[GG * DD];      // global_add_pool
__device__ float g_Wp[2 * NCH * 4096];   // fragment-permuted mlp2 weights+bias (tf32)

// The ONLY inline asm in this module: the tensor-core MMA itself.
#define MMA4(C, a0, a1, a2, a3, b0, b1)                                         \
    asm volatile(                                                               \
        "mma.sync.aligned.m16n8k8.row.col.f32.tf32.tf32.f32 "                   \
        "{%0,%1,%2,%3}, {%4,%5,%6,%7}, {%8,%9}, {%0,%1,%2,%3};"                 \
        : "+f"(C.x), "+f"(C.y), "+f"(C.z), "+f"(C.w)                            \
        : "r"(a0), "r"(a1), "r"(a2), "r"(a3), "r"(b0), "r"(b1))

// B fragment fetched straight from global (L2-resident, L1-shared across warps).
#define MMA_G(ntg, C)                                                           \
    do {                                                                        \
        float2 bb = __ldg((const float2*)(Wg + ((s * 8 + (ntg)) * 32 + lane) * 2)); \
        MMA4(C, a0, a1, a2, a3, __float_as_uint(bb.x), __float_as_uint(bb.y));  \
    } while (0)

// ---------------- tiny utility kernels ----------------
__global__ void k_zero_aggr() { g_aggr[blockIdx.x * blockDim.x + threadIdx.x] = 0.f; }
__global__ void k_zero_pooled() { g_pooled[blockIdx.x * blockDim.x + threadIdx.x] = 0.f; }

__global__ void k_lin0(const float* __restrict__ x, const float* __restrict__ w,
                       const float* __restrict__ b) {
    int idx = blockIdx.x * blockDim.x + threadIdx.x;
    int n = idx >> 6, o = idx & 63;
    float a = b[o];
#pragma unroll
    for (int f = 0; f < 16; f++) a += x[n * 16 + f] * w[o * 16 + f];
    g_h[idx] = fmaxf(a, 0.f);
}

__global__ void k_emlp(const float* __restrict__ ea, const float* __restrict__ w,
                       const float* __restrict__ b) {
    int idx = blockIdx.x * blockDim.x + threadIdx.x;
    int e = idx >> 6, c = idx & 63;
    float a = b[c];
#pragma unroll
    for (int k = 0; k < 6; k++) a += ea[e * 6 + k] * w[c * 6 + k];
    g_ef[idx] = fmaxf(a, 0.f);
}

// Permute mlp2 (and bias as chunk 64) into per-fragment order, tf32-rounded (pure C).
//   ch<64:  B[k=c][n=o] = W2[l][(ch*64+o)*64 + c], c = s*8+tig+4j, o = nt*8+gid
//   ch==64: B[k=i][n=o] = b2[l][i*64+o],           i = s*8+tig+4j
__global__ void k_perm(const float* __restrict__ w2, const float* __restrict__ b2) {
    int idx = blockIdx.x * blockDim.x + threadIdx.x;   // 2*65*4096
    int l = idx / (NCH * 4096);
    int r = idx % (NCH * 4096);
    int ch = r >> 12, q = r & 4095;
    int j = q & 1, lane = (q >> 1) & 31, nt = (q >> 6) & 7, s = q >> 9;
    int gid = lane >> 2, tig = lane & 3;
    int k = s * 8 + tig + 4 * j;
    int o = nt * 8 + gid;
    float val;
    if (ch < 64) val = w2[l * 262144 + (ch * 64 + o) * 64 + k];
    else         val = b2[l * 4096 + k * 64 + o];
    // round-to-nearest-even into tf32 (drop low 13 mantissa bits), no asm
    uint32_t bits = __float_as_uint(val);
    bits = (bits + 0x00000FFFu + ((bits >> 13) & 1u)) & 0xFFFFE000u;
    g_Wp[idx] = __uint_as_float(bits);
}

// ---------------- NNConv message GEMM via tf32 mma.sync ----------------
// Block: 64 edges x 64 outputs, 8 warps = 4 m-tiles(16) x 2 n-halves(32).
// K = 65*64. A chunk (ch<64): A[m,c] = u[m,ch]*v[m,c] built in registers.
// Chunk 64 (bias): A[m,i] = u[m,i]. B fragments stream from L2 via __ldg.
// NOTE: layer index passed as int; g_Wp offset computed IN DEVICE CODE
// (host-side arithmetic on a __device__ symbol yields the host shadow address).
#define UT_S 65
#define VS_S 68

__global__ void k_msg_mma(int l, const int* __restrict__ ei) {
    __shared__ float Ut[64 * UT_S];   // [i][m] u transposed
    __shared__ float Vs[MT * VS_S];   // [m][c] edge features

    const float* __restrict__ Wp = g_Wp + l * (NCH * 4096);

    const int t = threadIdx.x;
    const int wid = t >> 5, lane = t & 31;
    const int gid = lane >> 2, tig = lane & 3;
    const int e0 = blockIdx.x * MT;
    const int mw = (wid & 3) * 16;   // m tile origin
    const int nh = wid >> 2;         // n half (0 or 1)
    const int rl = mw + gid, rh = rl + 8;

    // Stage U (transposed, gathered h rows) and V tiles.
#pragma unroll
    for (int p = 0; p < 4; p++) {
        int idx = t + p * 256;
        int m = idx >> 4, q = idx & 15;
        int s_ = ei[e0 + m];
        float4 u4 = *(const float4*)(g_h + (size_t)s_ * 64 + q * 4);
        Ut[(q * 4 + 0) * UT_S + m] = u4.x;
        Ut[(q * 4 + 1) * UT_S + m] = u4.y;
        Ut[(q * 4 + 2) * UT_S + m] = u4.z;
        Ut[(q * 4 + 3) * UT_S + m] = u4.w;
        float4 v4 = *(const float4*)(g_ef + (size_t)(e0 + m) * 64 + q * 4);
        *(float4*)(Vs + m * VS_S + q * 4) = v4;
    }
    __syncthreads();

    float4 A0 = {0.f, 0.f, 0.f, 0.f}, A1 = A0, A2 = A0, A3 = A0;

#pragma unroll 1
    for (int ch = 0; ch < 64; ch++) {
        const float* Wg = Wp + ch * 4096;
        const float ua = Ut[ch * UT_S + rl];
        const float ub = Ut[ch * UT_S + rh];
#pragma unroll 2
        for (int s = 0; s < 8; s++) {
            const int c0 = s * 8 + tig;
            uint32_t a0 = __float_as_uint(ua * Vs[rl * VS_S + c0]);
            uint32_t a1 = __float_as_uint(ub * Vs[rh * VS_S + c0]);
            uint32_t a2 = __float_as_uint(ua * Vs[rl * VS_S + c0 + 4]);
            uint32_t a3 = __float_as_uint(ub * Vs[rh * VS_S + c0 + 4]);
            MMA_G(nh * 4 + 0, A0); MMA_G(nh * 4 + 1, A1);
            MMA_G(nh * 4 + 2, A2); MMA_G(nh * 4 + 3, A3);
        }
    }

    // Bias chunk (64): A[m,i] = u[m,i]
    {
        const float* Wg = Wp + 64 * 4096;
#pragma unroll 2
        for (int s = 0; s < 8; s++) {
            const int c0 = s * 8 + tig;
            uint32_t a0 = __float_as_uint(Ut[c0 * UT_S + rl]);
            uint32_t a1 = __float_as_uint(Ut[c0 * UT_S + rh]);
            uint32_t a2 = __float_as_uint(Ut[(c0 + 4) * UT_S + rl]);
            uint32_t a3 = __float_as_uint(Ut[(c0 + 4) * UT_S + rh]);
            MMA_G(nh * 4 + 0, A0); MMA_G(nh * 4 + 1, A1);
            MMA_G(nh * 4 + 2, A2); MMA_G(nh * 4 + 3, A3);
        }
    }

    // Epilogue: scatter-add into aggr[dst] (plain atomics, R1-proven).
    {
        int dlo = ei[EE + e0 + rl];
        int dhi = ei[EE + e0 + rh];
        float* plo = g_aggr + (size_t)dlo * 64 + nh * 32 + 2 * tig;
        float* phi = g_aggr + (size_t)dhi * 64 + nh * 32 + 2 * tig;
        atomicAdd(plo + 0,  A0.x); atomicAdd(plo + 1,  A0.y);
        atomicAdd(phi + 0,  A0.z); atomicAdd(phi + 1,  A0.w);
        atomicAdd(plo + 8,  A1.x); atomicAdd(plo + 9,  A1.y);
        atomicAdd(phi + 8,  A1.z); atomicAdd(phi + 9,  A1.w);
        atomicAdd(plo + 16, A2.x); atomicAdd(plo + 17, A2.y);
        atomicAdd(phi + 16, A2.z); atomicAdd(phi + 17, A2.w);
        atomicAdd(plo + 24, A3.x); atomicAdd(plo + 25, A3.y);
        atomicAdd(phi + 24, A3.z); atomicAdd(phi + 25, A3.w);
    }
}

// ---------------- per-node: root + bias + relu + BN + GRU step ----------------
__global__ void k_node(const float* __restrict__ root_w, const float* __restrict__ conv_b,
                       const float* __restrict__ bn, const float* __restrict__ wih,
                       const float* __restrict__ whh, const float* __restrict__ bih,
                       const float* __restrict__ bhh) {
    __shared__ float hrow[64], mrow[64];
    int n = blockIdx.x, o = threadIdx.x;
    float hv = g_h[n * 64 + o];
    hrow[o] = hv;
    __syncthreads();
    float acc = g_aggr[n * 64 + o] + conv_b[o];
#pragma unroll 16
    for (int i = 0; i < 64; i++) acc += hrow[i] * root_w[i * 64 + o];
    acc = fmaxf(acc, 0.f);
    acc = (acc - bn[128 + o]) * rsqrtf(bn[192 + o] + BN_EPS) * bn[o] + bn[64 + o];
    mrow[o] = acc;
    __syncthreads();
    float gir = bih[o], giz = bih[64 + o], gin = bih[128 + o];
    float ghr = bhh[o], ghz = bhh[64 + o], ghn = bhh[128 + o];
#pragma unroll 8
    for (int i = 0; i < 64; i++) {
        float mi = mrow[i], hi = hrow[i];
        gir += mi * wih[o * 64 + i];
        giz += mi * wih[(64 + o) * 64 + i];
        gin += mi * wih[(128 + o) * 64 + i];
        ghr += hi * whh[o * 64 + i];
        ghz += hi * whh[(64 + o) * 64 + i];
        ghn += hi * whh[(128 + o) * 64 + i];
    }
    float r = 1.f / (1.f + expf(-(gir + ghr)));
    float z = 1.f / (1.f + expf(-(giz + ghz)));
    float nv = tanhf(gin + r * ghn);
    g_h[n * 64 + o] = (1.f - z) * nv + z * hv;
}

// ---------------- GraphConv scatter: aggr[dst] += h[src] ----------------
__global__ void k_gcsc(const int* __restrict__ ei) {
    int idx = blockIdx.x * blockDim.x + threadIdx.x;
    int e = idx >> 6, o = idx & 63;
    int s = ei[e], d = ei[EE + e];
    atomicAdd(&g_aggr[d * 64 + o], g_h[s * 64 + o]);
}

// ---------------- GraphConv linear + BN + pool scatter ----------------
__global__ void k_gconv(const float* __restrict__ relw, const float* __restrict__ relb,
                        const float* __restrict__ rootw, const float* __restrict__ bnl,
                        const int* __restrict__ batch) {
    __shared__ float arow[64], hrow[64];
    int n = blockIdx.x, o = threadIdx.x;
    arow[o] = g_aggr[n * 64 + o];
    hrow[o] = g_h[n * 64 + o];
    __syncthreads();
    float a = relb[o];
#pragma unroll 16
    for (int i = 0; i < 64; i++)
        a += arow[i] * relw[o * 64 + i] + hrow[i] * rootw[o * 64 + i];
    a = fmaxf(a, 0.f);
    a = (a - bnl[128 + o]) * rsqrtf(bnl[192 + o] + BN_EPS) * bnl[o] + bnl[64 + o];
    atomicAdd(&g_pooled[batch[n] * 64 + o], a);
}

// ---------------- FC head ----------------
__global__ void k_head(const float* __restrict__ fc1_w, const float* __restrict__ fc1_b,
                       const float* __restrict__ fcbn1, const float* __restrict__ fc2_w,
                       const float* __restrict__ fc2_b, const float* __restrict__ fcbn2,
                       const float* __restrict__ fcl_w, const float* __restrict__ fcl_b,
                       float* __restrict__ out) {
    __shared__ float prow[64], f1[256], f2[128], red[256];
    int g = blockIdx.x, t = threadIdx.x;
    if (t < 64) prow[t] = g_pooled[g * 64 + t];
    __syncthreads();
    {
        float a = fc1_b[t];
#pragma unroll 16
        for (int i = 0; i < 64; i++) a += prow[i] * fc1_w[t * 64 + i];
        a = fmaxf(a, 0.f);
        a = (a - fcbn1[512 + t]) * rsqrtf(fcbn1[768 + t] + BN_EPS) * fcbn1[t] + fcbn1[256 + t];
        f1[t] = a;
    }
    __syncthreads();
    if (t < 128) {
        float a = fc2_b[t];
#pragma unroll 16
        for (int i = 0; i < 256; i++) a += f1[i] * fc2_w[t * 256 + i];
        a = fmaxf(a, 0.f);
        a = (a - fcbn2[256 + t]) * rsqrtf(fcbn2[384 + t] + BN_EPS) * fcbn2[t] + fcbn2[128 + t];
        f2[t] = a;
    }
    __syncthreads();
    red[t] = (t < 128) ? f2[t] * fcl_w[t] : 0.f;
    __syncthreads();
    for (int s = 128; s > 0; s >>= 1) {
        if (t < s) red[t] += red[t + s];
        __syncthreads();
    }
    if (t == 0) out[g] = red[0] + fcl_b[0];
}

// ---------------- launcher ----------------
extern "C" void kernel_launch(void* const* d_in, const int* in_sizes, int n_in,
                              void* d_out, int out_size) {
    const float* x        = (const float*)d_in[0];
    const float* edge_attr= (const float*)d_in[1];
    const float* lin0_w   = (const float*)d_in[2];
    const float* lin0_b   = (const float*)d_in[3];
    const float* mlp1_w   = (const float*)d_in[4];
    const float* mlp1_b   = (const float*)d_in[5];
    const float* mlp2_w   = (const float*)d_in[6];
    const float* mlp2_b   = (const float*)d_in[7];
    const float* root_w   = (const float*)d_in[8];
    const float* conv_b   = (const float*)d_in[9];
    const float* bn       = (const float*)d_in[10];
    const float* gru_wih  = (const float*)d_in[11];
    const float* gru_whh  = (const float*)d_in[12];
    const float* gru_bih  = (const float*)d_in[13];
    const float* gru_bhh  = (const float*)d_in[14];
    const float* gc_rel_w = (const float*)d_in[15];
    const float* gc_rel_b = (const float*)d_in[16];
    const float* gc_root_w= (const float*)d_in[17];
    const float* bnl      = (const float*)d_in[18];
    const float* fc1_w    = (const float*)d_in[19];
    const float* fc1_b    = (const float*)d_in[20];
    const float* fcbn1    = (const float*)d_in[21];
    const float* fc2_w    = (const float*)d_in[22];
    const float* fc2_b    = (const float*)d_in[23];
    const float* fcbn2    = (const float*)d_in[24];
    const float* fcl_w    = (const float*)d_in[25];
    const float* fcl_b    = (const float*)d_in[26];
    const int*   ei       = (const int*)d_in[27];
    const int*   batch    = (const int*)d_in[28];
    float* out = (float*)d_out;

    k_perm<<<(2 * NCH * 4096) / 256, 256>>>(mlp2_w, mlp2_b);
    k_lin0<<<(NN * DD) / 256, 256>>>(x, lin0_w, lin0_b);

    for (int l = 0; l < 2; l++) {
        k_emlp<<<(EE * DD) / 256, 256>>>(edge_attr, mlp1_w + l * 64 * 6, mlp1_b + l * 64);
        k_zero_aggr<<<(NN * DD) / 256, 256>>>();
        k_msg_mma<<<EE / MT, 256>>>(l, ei);
        k_node<<<NN, 64>>>(root_w + l * 4096, conv_b + l * 64, bn + l * 256,
                           gru_wih + l * 192 * 64, gru_whh + l * 192 * 64,
                           gru_bih + l * 192, gru_bhh + l * 192);
    }

    k_zero_aggr<<<(NN * DD) / 256, 256>>>();
    k_gcsc<<<(EE * DD) / 256, 256>>>(ei);
    k_zero_pooled<<<(GG * DD) / 256, 256>>>();
    k_gconv<<<NN, 64>>>(gc_rel_w, gc_rel_b, gc_root_w, bnl, batch);
    k_head<<<GG, 256>>>(fc1_w, fc1_b, fcbn1, fc2_w, fc2_b, fcbn2, fcl_w, fcl_b, out);
}

// round 11
// speedup vs baseline: 1.3317x; 1.2874x over previous
#include <cuda_runtime.h>
#include <math.h>
#include <stdint.h>

#define NN 16384
#define EE 65536
#define DD 64
#define GG 512
#define BN_EPS 1e-5f
#define NCH 65           // 64 uv-chunks + 1 bias chunk
#define MT 128           // edges per block in mma kernel

// ---------------- scratch (no allocations allowed) ----------------
__device__ float g_h[NN * DD];           // node features / GRU hidden
__device__ float g_ef[EE * DD];          // edge MLP1 output
__device__ float g_aggr[NN * DD];        // scatter-add target
__device__ float g_pooled[GG * DD];      // global_add_pool
__device__ float g_Wp[2 * NCH * 4096];   // fragment-permuted mlp2 weights+bias (tf32)

// ---------------- helpers ----------------
__device__ __forceinline__ uint32_t smem_u32(const void* p) {
    uint32_t a;
    asm("{ .reg .u64 t; cvta.to.shared.u64 t, %1; cvt.u32.u64 %0, t; }" : "=r"(a) : "l"(p));
    return a;
}

// MMA on a named float4 accumulator — no address-taking, no local arrays.
#define MMA4(C, a0, a1, a2, a3, b0, b1)                                         \
    asm volatile(                                                               \
        "mma.sync.aligned.m16n8k8.row.col.f32.tf32.tf32.f32 "                   \
        "{%0,%1,%2,%3}, {%4,%5,%6,%7}, {%8,%9}, {%0,%1,%2,%3};"                 \
        : "+f"(C.x), "+f"(C.y), "+f"(C.z), "+f"(C.w)                            \
        : "r"(a0), "r"(a1), "r"(a2), "r"(a3), "r"(b0), "r"(b1))

// B fragment from SMEM-staged chunk (conflict-free LDS.64).
#define MMA_NT(nt, C)                                                           \
    do {                                                                        \
        float2 bb = *(const float2*)(WB + ((s * 8 + (nt)) * 32 + lane) * 2);    \
        MMA4(C, a0, a1, a2, a3, __float_as_uint(bb.x), __float_as_uint(bb.y));  \
    } while (0)

#define RED_NT(nt, C)                                                           \
    do {                                                                        \
        asm volatile("red.global.add.v2.f32 [%0], {%1,%2};"                     \
                     :: "l"(plo + (nt) * 8), "f"(C.x), "f"(C.y) : "memory");    \
        asm volatile("red.global.add.v2.f32 [%0], {%1,%2};"                     \
                     :: "l"(phi + (nt) * 8), "f"(C.z), "f"(C.w) : "memory");    \
    } while (0)

// ---------------- tiny utility kernels ----------------
__global__ void k_zero_aggr() { g_aggr[blockIdx.x * blockDim.x + threadIdx.x] = 0.f; }
__global__ void k_zero_pooled() { g_pooled[blockIdx.x * blockDim.x + threadIdx.x] = 0.f; }

__global__ void k_lin0(const float* __restrict__ x, const float* __restrict__ w,
                       const float* __restrict__ b) {
    int idx = blockIdx.x * blockDim.x + threadIdx.x;
    int n = idx >> 6, o = idx & 63;
    float a = b[o];
#pragma unroll
    for (int f = 0; f < 16; f++) a += x[n * 16 + f] * w[o * 16 + f];
    g_h[idx] = fmaxf(a, 0.f);
}

__global__ void k_emlp(const float* __restrict__ ea, const float* __restrict__ w,
                       const float* __restrict__ b) {
    int idx = blockIdx.x * blockDim.x + threadIdx.x;
    int e = idx >> 6, c = idx & 63;
    float a = b[c];
#pragma unroll
    for (int k = 0; k < 6; k++) a += ea[e * 6 + k] * w[c * 6 + k];
    g_ef[idx] = fmaxf(a, 0.f);
}

// Permute mlp2 (and bias as chunk 64) into per-fragment order, tf32-rounded (pure C).
//   ch<64:  B[k=c][n=o] = W2[l][(ch*64+o)*64 + c], c = s*8+tig+4j, o = nt*8+gid
//   ch==64: B[k=i][n=o] = b2[l][i*64+o],           i = s*8+tig+4j
__global__ void k_perm(const float* __restrict__ w2, const float* __restrict__ b2) {
    int idx = blockIdx.x * blockDim.x + threadIdx.x;   // 2*65*4096
    int l = idx / (NCH * 4096);
    int r = idx % (NCH * 4096);
    int ch = r >> 12, q = r & 4095;
    int j = q & 1, lane = (q >> 1) & 31, nt = (q >> 6) & 7, s = q >> 9;
    int gid = lane >> 2, tig = lane & 3;
    int k = s * 8 + tig + 4 * j;
    int o = nt * 8 + gid;
    float val;
    if (ch < 64) val = w2[l * 262144 + (ch * 64 + o) * 64 + k];
    else         val = b2[l * 4096 + k * 64 + o];
    uint32_t bits = __float_as_uint(val);
    bits = (bits + 0x00000FFFu + ((bits >> 13) & 1u)) & 0xFFFFE000u;
    g_Wp[idx] = __uint_as_float(bits);
}

// ---------------- NNConv message GEMM via tf32 mma.sync ----------------
// Block: 128 edges x 64 outputs, 8 warps (warp tile 16m x 64n), K = 65*64.
// A chunk (ch<64): A[m,c] = u[m,ch]*v[m,c] built per-fragment in registers.
// Chunk 64 (bias): A[m,i] = u[m,i]. B chunks staged via cp.async double buffer.
// Dynamic SMEM: Ut[64*129] | Vs[128*68] | Wb[2*4096]  = 100608 B (2 CTAs/SM).
#define UT_S 129
#define VS_S 68
#define OFF_VS (64 * UT_S)            // float offset
#define OFF_WB (OFF_VS + MT * VS_S)   // float offset
#define MSG_SMEM ((OFF_WB + 2 * 4096) * 4)

__global__ void k_msg_mma(int l, const int* __restrict__ ei) {
    extern __shared__ float smf[];
    float* Ut = smf;                    // [i][m] u transposed
    float* Vs = smf + OFF_VS;           // [m][c] edge features
    float* Wb = smf + OFF_WB;           // [2][4096] W double buffer
    const uint32_t wsm = smem_u32(Wb);

    const float* __restrict__ Wp = g_Wp + l * (NCH * 4096);

    const int t = threadIdx.x;
    const int wid = t >> 5, lane = t & 31;
    const int gid = lane >> 2, tig = lane & 3;
    const int e0 = blockIdx.x * MT;
    const int rl = wid * 16 + gid, rh = rl + 8;

    // Prefetch W chunk 0 (overlaps U/V staging)
#pragma unroll
    for (int p = 0; p < 4; p++) {
        int i4 = t + p * 256;
        asm volatile("cp.async.cg.shared.global [%0], [%1], 16;"
                     :: "r"(wsm + i4 * 16), "l"(Wp + i4 * 4) : "memory");
    }
    asm volatile("cp.async.commit_group;" ::: "memory");

    // Stage U (transposed, gathered h rows) and V tiles.
#pragma unroll
    for (int p = 0; p < 8; p++) {
        int idx = t + p * 256;
        int m = idx >> 4, q = idx & 15;
        int s_ = ei[e0 + m];
        float4 u4 = *(const float4*)(g_h + (size_t)s_ * 64 + q * 4);
        Ut[(q * 4 + 0) * UT_S + m] = u4.x;
        Ut[(q * 4 + 1) * UT_S + m] = u4.y;
        Ut[(q * 4 + 2) * UT_S + m] = u4.z;
        Ut[(q * 4 + 3) * UT_S + m] = u4.w;
        float4 v4 = *(const float4*)(g_ef + (size_t)(e0 + m) * 64 + q * 4);
        *(float4*)(Vs + m * VS_S + q * 4) = v4;
    }

    float4 A0 = {0.f, 0.f, 0.f, 0.f}, A1 = A0, A2 = A0, A3 = A0;
    float4 A4 = A0, A5 = A0, A6 = A0, A7 = A0;

#pragma unroll 1
    for (int ch = 0; ch < 64; ch++) {
        asm volatile("cp.async.wait_group 0;" ::: "memory");
        __syncthreads();
        {   // prefetch next chunk (incl. bias chunk 64) into other buffer
            const float* src = Wp + (ch + 1) * 4096;
            uint32_t dst = wsm + ((ch + 1) & 1) * 16384;
#pragma unroll
            for (int p = 0; p < 4; p++) {
                int i4 = t + p * 256;
                asm volatile("cp.async.cg.shared.global [%0], [%1], 16;"
                             :: "r"(dst + i4 * 16), "l"(src + i4 * 4) : "memory");
            }
            asm volatile("cp.async.commit_group;" ::: "memory");
        }
        const float* WB = Wb + (ch & 1) * 4096;
        const float ua = Ut[ch * UT_S + rl];
        const float ub = Ut[ch * UT_S + rh];
#pragma unroll 2
        for (int s = 0; s < 8; s++) {
            const int c0 = s * 8 + tig;
            uint32_t a0 = __float_as_uint(ua * Vs[rl * VS_S + c0]);
            uint32_t a1 = __float_as_uint(ub * Vs[rh * VS_S + c0]);
            uint32_t a2 = __float_as_uint(ua * Vs[rl * VS_S + c0 + 4]);
            uint32_t a3 = __float_as_uint(ub * Vs[rh * VS_S + c0 + 4]);
            MMA_NT(0, A0); MMA_NT(1, A1); MMA_NT(2, A2); MMA_NT(3, A3);
            MMA_NT(4, A4); MMA_NT(5, A5); MMA_NT(6, A6); MMA_NT(7, A7);
        }
    }

    // Bias chunk (64): A[m,i] = u[m,i]; chunk 64 -> buffer 0
    asm volatile("cp.async.wait_group 0;" ::: "memory");
    __syncthreads();
    {
        const float* WB = Wb;
#pragma unroll 2
        for (int s = 0; s < 8; s++) {
            const int c0 = s * 8 + tig;
            uint32_t a0 = __float_as_uint(Ut[c0 * UT_S + rl]);
            uint32_t a1 = __float_as_uint(Ut[c0 * UT_S + rh]);
            uint32_t a2 = __float_as_uint(Ut[(c0 + 4) * UT_S + rl]);
            uint32_t a3 = __float_as_uint(Ut[(c0 + 4) * UT_S + rh]);
            MMA_NT(0, A0); MMA_NT(1, A1); MMA_NT(2, A2); MMA_NT(3, A3);
            MMA_NT(4, A4); MMA_NT(5, A5); MMA_NT(6, A6); MMA_NT(7, A7);
        }
    }

    // Epilogue: scatter-add into aggr[dst].
    {
        int dlo = ei[EE + e0 + rl];
        int dhi = ei[EE + e0 + rh];
        float* plo = g_aggr + (size_t)dlo * 64 + 2 * tig;
        float* phi = g_aggr + (size_t)dhi * 64 + 2 * tig;
        RED_NT(0, A0); RED_NT(1, A1); RED_NT(2, A2); RED_NT(3, A3);
        RED_NT(4, A4); RED_NT(5, A5); RED_NT(6, A6); RED_NT(7, A7);
    }
}

// ---------------- per-node: root + bias + relu + BN + GRU step ----------------
__global__ void k_node(const float* __restrict__ root_w, const float* __restrict__ conv_b,
                       const float* __restrict__ bn, const float* __restrict__ wih,
                       const float* __restrict__ whh, const float* __restrict__ bih,
                       const float* __restrict__ bhh) {
    __shared__ float hrow[64], mrow[64];
    int n = blockIdx.x, o = threadIdx.x;
    float hv = g_h[n * 64 + o];
    hrow[o] = hv;
    __syncthreads();
    float acc = g_aggr[n * 64 + o] + conv_b[o];
#pragma unroll 16
    for (int i = 0; i < 64; i++) acc += hrow[i] * root_w[i * 64 + o];
    acc = fmaxf(acc, 0.f);
    acc = (acc - bn[128 + o]) * rsqrtf(bn[192 + o] + BN_EPS) * bn[o] + bn[64 + o];
    mrow[o] = acc;
    __syncthreads();
    float gir = bih[o], giz = bih[64 + o], gin = bih[128 + o];
    float ghr = bhh[o], ghz = bhh[64 + o], ghn = bhh[128 + o];
#pragma unroll 8
    for (int i = 0; i < 64; i++) {
        float mi = mrow[i], hi = hrow[i];
        gir += mi * wih[o * 64 + i];
        giz += mi * wih[(64 + o) * 64 + i];
        gin += mi * wih[(128 + o) * 64 + i];
        ghr += hi * whh[o * 64 + i];
        ghz += hi * whh[(64 + o) * 64 + i];
        ghn += hi * whh[(128 + o) * 64 + i];
    }
    float r = 1.f / (1.f + expf(-(gir + ghr)));
    float z = 1.f / (1.f + expf(-(giz + ghz)));
    float nv = tanhf(gin + r * ghn);
    g_h[n * 64 + o] = (1.f - z) * nv + z * hv;
}

// ---------------- GraphConv scatter: aggr[dst] += h[src] ----------------
__global__ void k_gcsc(const int* __restrict__ ei) {
    int idx = blockIdx.x * blockDim.x + threadIdx.x;
    int e = idx >> 6, o = idx & 63;
    int s = ei[e], d = ei[EE + e];
    atomicAdd(&g_aggr[d * 64 + o], g_h[s * 64 + o]);
}

// ---------------- GraphConv linear + BN + pool scatter ----------------
__global__ void k_gconv(const float* __restrict__ relw, const float* __restrict__ relb,
                        const float* __restrict__ rootw, const float* __restrict__ bnl,
                        const int* __restrict__ batch) {
    __shared__ float arow[64], hrow[64];
    int n = blockIdx.x, o = threadIdx.x;
    arow[o] = g_aggr[n * 64 + o];
    hrow[o] = g_h[n * 64 + o];
    __syncthreads();
    float a = relb[o];
#pragma unroll 16
    for (int i = 0; i < 64; i++)
        a += arow[i] * relw[o * 64 + i] + hrow[i] * rootw[o * 64 + i];
    a = fmaxf(a, 0.f);
    a = (a - bnl[128 + o]) * rsqrtf(bnl[192 + o] + BN_EPS) * bnl[o] + bnl[64 + o];
    atomicAdd(&g_pooled[batch[n] * 64 + o], a);
}

// ---------------- FC head ----------------
__global__ void k_head(const float* __restrict__ fc1_w, const float* __restrict__ fc1_b,
                       const float* __restrict__ fcbn1, const float* __restrict__ fc2_w,
                       const float* __restrict__ fc2_b, const float* __restrict__ fcbn2,
                       const float* __restrict__ fcl_w, const float* __restrict__ fcl_b,
                       float* __restrict__ out) {
    __shared__ float prow[64], f1[256], f2[128], red[256];
    int g = blockIdx.x, t = threadIdx.x;
    if (t < 64) prow[t] = g_pooled[g * 64 + t];
    __syncthreads();
    {
        float a = fc1_b[t];
#pragma unroll 16
        for (int i = 0; i < 64; i++) a += prow[i] * fc1_w[t * 64 + i];
        a = fmaxf(a, 0.f);
        a = (a - fcbn1[512 + t]) * rsqrtf(fcbn1[768 + t] + BN_EPS) * fcbn1[t] + fcbn1[256 + t];
        f1[t] = a;
    }
    __syncthreads();
    if (t < 128) {
        float a = fc2_b[t];
#pragma unroll 16
        for (int i = 0; i < 256; i++) a += f1[i] * fc2_w[t * 256 + i];
        a = fmaxf(a, 0.f);
        a = (a - fcbn2[256 + t]) * rsqrtf(fcbn2[384 + t] + BN_EPS) * fcbn2[t] + fcbn2[128 + t];
        f2[t] = a;
    }
    __syncthreads();
    red[t] = (t < 128) ? f2[t] * fcl_w[t] : 0.f;
    __syncthreads();
    for (int s = 128; s > 0; s >>= 1) {
        if (t < s) red[t] += red[t + s];
        __syncthreads();
    }
    if (t == 0) out[g] = red[0] + fcl_b[0];
}

// ---------------- launcher ----------------
extern "C" void kernel_launch(void* const* d_in, const int* in_sizes, int n_in,
                              void* d_out, int out_size) {
    const float* x        = (const float*)d_in[0];
    const float* edge_attr= (const float*)d_in[1];
    const float* lin0_w   = (const float*)d_in[2];
    const float* lin0_b   = (const float*)d_in[3];
    const float* mlp1_w   = (const float*)d_in[4];
    const float* mlp1_b   = (const float*)d_in[5];
    const float* mlp2_w   = (const float*)d_in[6];
    const float* mlp2_b   = (const float*)d_in[7];
    const float* root_w   = (const float*)d_in[8];
    const float* conv_b   = (const float*)d_in[9];
    const float* bn       = (const float*)d_in[10];
    const float* gru_wih  = (const float*)d_in[11];
    const float* gru_whh  = (const float*)d_in[12];
    const float* gru_bih  = (const float*)d_in[13];
    const float* gru_bhh  = (const float*)d_in[14];
    const float* gc_rel_w = (const float*)d_in[15];
    const float* gc_rel_b = (const float*)d_in[16];
    const float* gc_root_w= (const float*)d_in[17];
    const float* bnl      = (const float*)d_in[18];
    const float* fc1_w    = (const float*)d_in[19];
    const float* fc1_b    = (const float*)d_in[20];
    const float* fcbn1    = (const float*)d_in[21];
    const float* fc2_w    = (const float*)d_in[22];
    const float* fc2_b    = (const float*)d_in[23];
    const float* fcbn2    = (const float*)d_in[24];
    const float* fcl_w    = (const float*)d_in[25];
    const float* fcl_b    = (const float*)d_in[26];
    const int*   ei       = (const int*)d_in[27];
    const int*   batch    = (const int*)d_in[28];
    float* out = (float*)d_out;

    cudaFuncSetAttribute(k_msg_mma, cudaFuncAttributeMaxDynamicSharedMemorySize, MSG_SMEM);

    k_perm<<<(2 * NCH * 4096) / 256, 256>>>(mlp2_w, mlp2_b);
    k_lin0<<<(NN * DD) / 256, 256>>>(x, lin0_w, lin0_b);

    for (int l = 0; l < 2; l++) {
        k_emlp<<<(EE * DD) / 256, 256>>>(edge_attr, mlp1_w + l * 64 * 6, mlp1_b + l * 64);
        k_zero_aggr<<<(NN * DD) / 256, 256>>>();
        k_msg_mma<<<EE / MT, 256, MSG_SMEM>>>(l, ei);
        k_node<<<NN, 64>>>(root_w + l * 4096, conv_b + l * 64, bn + l * 256,
                           gru_wih + l * 192 * 64, gru_whh + l * 192 * 64,
                           gru_bih + l * 192, gru_bhh + l * 192);
    }

    k_zero_aggr<<<(NN * DD) / 256, 256>>>();
    k_gcsc<<<(EE * DD) / 256, 256>>>(ei);
    k_zero_pooled<<<(GG * DD) / 256, 256>>>();
    k_gconv<<<NN, 64>>>(gc_rel_w, gc_rel_b, gc_root_w, bnl, batch);
    k_head<<<GG, 256>>>(fc1_w, fc1_b, fcbn1, fc2_w, fc2_b, fcbn2, fcl_w, fcl_b, out);
}

// round 13
// speedup vs baseline: 7.5795x; 5.6914x over previous
#include <cuda_runtime.h>
#include <math.h>
#include <stdint.h>

#define NN 16384
#define EE 65536
#define DD 64
#define GG 512
#define BN_EPS 1e-5f
#define NCH 65           // 64 uv-chunks + 1 bias chunk
#define MT 128           // edges per block in mma kernel

// ---------------- scratch (no allocations allowed) ----------------
__device__ float g_h[NN * DD];           // node features / GRU hidden
__device__ float g_ef[EE * DD];          // edge MLP1 output
__device__ float g_aggr[NN * DD];        // scatter-add target
__device__ float g_pooled[GG * DD];      // global_add_pool
__device__ float g_Wp[2 * NCH * 4096];   // fragment-permuted mlp2 weights+bias (tf32)
__device__ float g_gruT[2 * 64 * 384];   // GRU weights transposed [l][i][ih/hh][gate][o]
__device__ float g_gcT[2 * 64 * 64];     // GraphConv rel/root transposed [mat][i][o]
__device__ float g_fc1T[64 * 256];       // fc1 transposed [i][t]
__device__ float g_fc2T[256 * 128];      // fc2 transposed [i][t]

// ---------------- helpers ----------------
__device__ __forceinline__ uint32_t smem_u32(const void* p) {
    uint32_t a;
    asm("{ .reg .u64 t; cvta.to.shared.u64 t, %1; cvt.u32.u64 %0, t; }" : "=r"(a) : "l"(p));
    return a;
}

#define MMA4(C, a0, a1, a2, a3, b0, b1)                                         \
    asm volatile(                                                               \
        "mma.sync.aligned.m16n8k8.row.col.f32.tf32.tf32.f32 "                   \
        "{%0,%1,%2,%3}, {%4,%5,%6,%7}, {%8,%9}, {%0,%1,%2,%3};"                 \
        : "+f"(C.x), "+f"(C.y), "+f"(C.z), "+f"(C.w)                            \
        : "r"(a0), "r"(a1), "r"(a2), "r"(a3), "r"(b0), "r"(b1))

#define MMA_NT(nt, C)                                                           \
    do {                                                                        \
        float2 bb = *(const float2*)(WB + ((s * 8 + (nt)) * 32 + lane) * 2);    \
        MMA4(C, a0, a1, a2, a3, __float_as_uint(bb.x), __float_as_uint(bb.y));  \
    } while (0)

#define RED_NT(nt, C)                                                           \
    do {                                                                        \
        asm volatile("red.global.add.v2.f32 [%0], {%1,%2};"                     \
                     :: "l"(plo + (nt) * 8), "f"(C.x), "f"(C.y) : "memory");    \
        asm volatile("red.global.add.v2.f32 [%0], {%1,%2};"                     \
                     :: "l"(phi + (nt) * 8), "f"(C.z), "f"(C.w) : "memory");    \
    } while (0)

// ---------------- prep: fragment-permute Wp + transpose small weights ----------------
//  [0, 532480)          : Wp (as before, tf32-rounded)
//  [532480, 581632)     : gruT  [l][i][half][gate][o]   (49152)
//  [581632, 589824)     : gcT   [mat][i][o]             (8192)
//  [589824, 606208)     : fc1T  [i][t]                  (16384)
//  [606208, 638976)     : fc2T  [i][t]                  (32768)
__global__ void k_perm(const float* __restrict__ w2, const float* __restrict__ b2,
                       const float* __restrict__ wih, const float* __restrict__ whh,
                       const float* __restrict__ relw, const float* __restrict__ rootw,
                       const float* __restrict__ fc1w, const float* __restrict__ fc2w) {
    int idx = blockIdx.x * blockDim.x + threadIdx.x;   // 638976 total
    if (idx < 532480) {
        int l = idx / (NCH * 4096);
        int r = idx % (NCH * 4096);
        int ch = r >> 12, q = r & 4095;
        int j = q & 1, lane = (q >> 1) & 31, nt = (q >> 6) & 7, s = q >> 9;
        int gid = lane >> 2, tig = lane & 3;
        int k = s * 8 + tig + 4 * j;
        int o = nt * 8 + gid;
        float val;
        if (ch < 64) val = w2[l * 262144 + (ch * 64 + o) * 64 + k];
        else         val = b2[l * 4096 + k * 64 + o];
        uint32_t bits = __float_as_uint(val);
        bits = (bits + 0x00000FFFu + ((bits >> 13) & 1u)) & 0xFFFFE000u;
        g_Wp[idx] = __uint_as_float(bits);
    } else if (idx < 581632) {
        int r = idx - 532480;
        int l = r / 24576; r %= 24576;
        int i = r / 384, q = r % 384;
        int half = q / 192, gate = (q % 192) / 64, o = q & 63;
        const float* src = half ? whh : wih;
        g_gruT[idx - 532480] = src[l * 12288 + (gate * 64 + o) * 64 + i];
    } else if (idx < 589824) {
        int r = idx - 581632;
        int mat = r / 4096; r %= 4096;
        int i = r >> 6, o = r & 63;
        g_gcT[idx - 581632] = (mat ? rootw : relw)[o * 64 + i];
    } else if (idx < 606208) {
        int r = idx - 589824;
        int i = r >> 8, t = r & 255;
        g_fc1T[r] = fc1w[t * 64 + i];
    } else {
        int r = idx - 606208;
        int i = r >> 7, t = r & 127;
        g_fc2T[r] = fc2w[t * 256 + i];
    }
}

__global__ void k_lin0(const float* __restrict__ x, const float* __restrict__ w,
                       const float* __restrict__ b) {
    int idx = blockIdx.x * blockDim.x + threadIdx.x;
    int n = idx >> 6, o = idx & 63;
    float a = b[o];
#pragma unroll
    for (int f = 0; f < 16; f++) a += x[n * 16 + f] * w[o * 16 + f];
    g_h[idx] = fmaxf(a, 0.f);
}

// edge MLP1 + fused g_aggr zero (aggr is 1/4 the index range)
__global__ void k_emlp(const float* __restrict__ ea, const float* __restrict__ w,
                       const float* __restrict__ b) {
    int idx = blockIdx.x * blockDim.x + threadIdx.x;
    int e = idx >> 6, c = idx & 63;
    float a = b[c];
#pragma unroll
    for (int k = 0; k < 6; k++) a += ea[e * 6 + k] * w[c * 6 + k];
    g_ef[idx] = fmaxf(a, 0.f);
    if (idx < NN * DD) g_aggr[idx] = 0.f;
}

// ---------------- NNConv message GEMM via tf32 mma.sync ----------------
#define UT_S 129
#define VS_S 68
#define OFF_VS (64 * UT_S)
#define OFF_WB (OFF_VS + MT * VS_S)
#define MSG_SMEM ((OFF_WB + 2 * 4096) * 4)

__global__ void k_msg_mma(int l, const int* __restrict__ ei) {
    extern __shared__ float smf[];
    float* Ut = smf;
    float* Vs = smf + OFF_VS;
    float* Wb = smf + OFF_WB;
    const uint32_t wsm = smem_u32(Wb);

    const float* __restrict__ Wp = g_Wp + l * (NCH * 4096);

    const int t = threadIdx.x;
    const int wid = t >> 5, lane = t & 31;
    const int gid = lane >> 2, tig = lane & 3;
    const int e0 = blockIdx.x * MT;
    const int rl = wid * 16 + gid, rh = rl + 8;

#pragma unroll
    for (int p = 0; p < 4; p++) {
        int i4 = t + p * 256;
        asm volatile("cp.async.cg.shared.global [%0], [%1], 16;"
                     :: "r"(wsm + i4 * 16), "l"(Wp + i4 * 4) : "memory");
    }
    asm volatile("cp.async.commit_group;" ::: "memory");

#pragma unroll
    for (int p = 0; p < 8; p++) {
        int idx = t + p * 256;
        int m = idx >> 4, q = idx & 15;
        int s_ = ei[e0 + m];
        float4 u4 = *(const float4*)(g_h + (size_t)s_ * 64 + q * 4);
        Ut[(q * 4 + 0) * UT_S + m] = u4.x;
        Ut[(q * 4 + 1) * UT_S + m] = u4.y;
        Ut[(q * 4 + 2) * UT_S + m] = u4.z;
        Ut[(q * 4 + 3) * UT_S + m] = u4.w;
        float4 v4 = *(const float4*)(g_ef + (size_t)(e0 + m) * 64 + q * 4);
        *(float4*)(Vs + m * VS_S + q * 4) = v4;
    }

    float4 A0 = {0.f, 0.f, 0.f, 0.f}, A1 = A0, A2 = A0, A3 = A0;
    float4 A4 = A0, A5 = A0, A6 = A0, A7 = A0;

#pragma unroll 1
    for (int ch = 0; ch < 64; ch++) {
        asm volatile("cp.async.wait_group 0;" ::: "memory");
        __syncthreads();
        {
            const float* src = Wp + (ch + 1) * 4096;
            uint32_t dst = wsm + ((ch + 1) & 1) * 16384;
#pragma unroll
            for (int p = 0; p < 4; p++) {
                int i4 = t + p * 256;
                asm volatile("cp.async.cg.shared.global [%0], [%1], 16;"
                             :: "r"(dst + i4 * 16), "l"(src + i4 * 4) : "memory");
            }
            asm volatile("cp.async.commit_group;" ::: "memory");
        }
        const float* WB = Wb + (ch & 1) * 4096;
        const float ua = Ut[ch * UT_S + rl];
        const float ub = Ut[ch * UT_S + rh];
#pragma unroll 2
        for (int s = 0; s < 8; s++) {
            const int c0 = s * 8 + tig;
            uint32_t a0 = __float_as_uint(ua * Vs[rl * VS_S + c0]);
            uint32_t a1 = __float_as_uint(ub * Vs[rh * VS_S + c0]);
            uint32_t a2 = __float_as_uint(ua * Vs[rl * VS_S + c0 + 4]);
            uint32_t a3 = __float_as_uint(ub * Vs[rh * VS_S + c0 + 4]);
            MMA_NT(0, A0); MMA_NT(1, A1); MMA_NT(2, A2); MMA_NT(3, A3);
            MMA_NT(4, A4); MMA_NT(5, A5); MMA_NT(6, A6); MMA_NT(7, A7);
        }
    }

    asm volatile("cp.async.wait_group 0;" ::: "memory");
    __syncthreads();
    {
        const float* WB = Wb;   // bias chunk 64 -> buffer 0
#pragma unroll 2
        for (int s = 0; s < 8; s++) {
            const int c0 = s * 8 + tig;
            uint32_t a0 = __float_as_uint(Ut[c0 * UT_S + rl]);
            uint32_t a1 = __float_as_uint(Ut[c0 * UT_S + rh]);
            uint32_t a2 = __float_as_uint(Ut[(c0 + 4) * UT_S + rl]);
            uint32_t a3 = __float_as_uint(Ut[(c0 + 4) * UT_S + rh]);
            MMA_NT(0, A0); MMA_NT(1, A1); MMA_NT(2, A2); MMA_NT(3, A3);
            MMA_NT(4, A4); MMA_NT(5, A5); MMA_NT(6, A6); MMA_NT(7, A7);
        }
    }

    {
        int dlo = ei[EE + e0 + rl];
        int dhi = ei[EE + e0 + rh];
        float* plo = g_aggr + (size_t)dlo * 64 + 2 * tig;
        float* phi = g_aggr + (size_t)dhi * 64 + 2 * tig;
        RED_NT(0, A0); RED_NT(1, A1); RED_NT(2, A2); RED_NT(3, A3);
        RED_NT(4, A4); RED_NT(5, A5); RED_NT(6, A6); RED_NT(7, A7);
    }
}

// ---------------- per-node: root + bias + relu + BN + GRU (coalesced weights) ----
// Also clears g_aggr after reading (fused zero for next consumer).
__global__ void k_node(int l, const float* __restrict__ root_w,
                       const float* __restrict__ conv_b, const float* __restrict__ bn,
                       const float* __restrict__ bih, const float* __restrict__ bhh) {
    __shared__ float hrow[64], mrow[64];
    const float* __restrict__ gT = g_gruT + l * (64 * 384);
    int n = blockIdx.x, o = threadIdx.x;
    float hv = g_h[n * 64 + o];
    hrow[o] = hv;
    __syncthreads();
    float acc = g_aggr[n * 64 + o] + conv_b[o];
    g_aggr[n * 64 + o] = 0.f;     // fused zero for next aggregation
#pragma unroll 16
    for (int i = 0; i < 64; i++) acc += hrow[i] * root_w[i * 64 + o];
    acc = fmaxf(acc, 0.f);
    acc = (acc - bn[128 + o]) * rsqrtf(bn[192 + o] + BN_EPS) * bn[o] + bn[64 + o];
    mrow[o] = acc;
    __syncthreads();
    float gir = bih[o], giz = bih[64 + o], gin = bih[128 + o];
    float ghr = bhh[o], ghz = bhh[64 + o], ghn = bhh[128 + o];
#pragma unroll 8
    for (int i = 0; i < 64; i++) {
        float mi = mrow[i], hi = hrow[i];
        const float* gi = gT + i * 384;
        gir += mi * gi[o];
        giz += mi * gi[64 + o];
        gin += mi * gi[128 + o];
        ghr += hi * gi[192 + o];
        ghz += hi * gi[256 + o];
        ghn += hi * gi[320 + o];
    }
    float r = 1.f / (1.f + expf(-(gir + ghr)));
    float z = 1.f / (1.f + expf(-(giz + ghz)));
    float nv = tanhf(gin + r * ghn);
    g_h[n * 64 + o] = (1.f - z) * nv + z * hv;
}

// ---------------- GraphConv scatter + fused pooled zero ----------------
__global__ void k_gcsc(const int* __restrict__ ei) {
    int idx = blockIdx.x * blockDim.x + threadIdx.x;
    int e = idx >> 6, o = idx & 63;
    int s = ei[e], d = ei[EE + e];
    atomicAdd(&g_aggr[d * 64 + o], g_h[s * 64 + o]);
    if (idx < GG * DD) g_pooled[idx] = 0.f;
}

// ---------------- GraphConv linear + BN + pool scatter (coalesced weights) -------
__global__ void k_gconv(const float* __restrict__ relb, const float* __restrict__ bnl,
                        const int* __restrict__ batch) {
    __shared__ float arow[64], hrow[64];
    int n = blockIdx.x, o = threadIdx.x;
    arow[o] = g_aggr[n * 64 + o];
    hrow[o] = g_h[n * 64 + o];
    __syncthreads();
    float a = relb[o];
#pragma unroll 16
    for (int i = 0; i < 64; i++)
        a += arow[i] * g_gcT[i * 64 + o] + hrow[i] * g_gcT[4096 + i * 64 + o];
    a = fmaxf(a, 0.f);
    a = (a - bnl[128 + o]) * rsqrtf(bnl[192 + o] + BN_EPS) * bnl[o] + bnl[64 + o];
    atomicAdd(&g_pooled[batch[n] * 64 + o], a);
}

// ---------------- FC head (coalesced transposed weights) ----------------
__global__ void k_head(const float* __restrict__ fc1_b, const float* __restrict__ fcbn1,
                       const float* __restrict__ fc2_b, const float* __restrict__ fcbn2,
                       const float* __restrict__ fcl_w, const float* __restrict__ fcl_b,
                       float* __restrict__ out) {
    __shared__ float prow[64], f1[256], f2[128], red[256];
    int g = blockIdx.x, t = threadIdx.x;
    if (t < 64) prow[t] = g_pooled[g * 64 + t];
    __syncthreads();
    {
        float a = fc1_b[t];
#pragma unroll 16
        for (int i = 0; i < 64; i++) a += prow[i] * g_fc1T[i * 256 + t];
        a = fmaxf(a, 0.f);
        a = (a - fcbn1[512 + t]) * rsqrtf(fcbn1[768 + t] + BN_EPS) * fcbn1[t] + fcbn1[256 + t];
        f1[t] = a;
    }
    __syncthreads();
    if (t < 128) {
        float a = fc2_b[t];
#pragma unroll 16
        for (int i = 0; i < 256; i++) a += f1[i] * g_fc2T[i * 128 + t];
        a = fmaxf(a, 0.f);
        a = (a - fcbn2[256 + t]) * rsqrtf(fcbn2[384 + t] + BN_EPS) * fcbn2[t] + fcbn2[128 + t];
        f2[t] = a;
    }
    __syncthreads();
    red[t] = (t < 128) ? f2[t] * fcl_w[t] : 0.f;
    __syncthreads();
    for (int s = 128; s > 0; s >>= 1) {
        if (t < s) red[t] += red[t + s];
        __syncthreads();
    }
    if (t == 0) out[g] = red[0] + fcl_b[0];
}

// ---------------- launcher ----------------
extern "C" void kernel_launch(void* const* d_in, const int* in_sizes, int n_in,
                              void* d_out, int out_size) {
    const float* x        = (const float*)d_in[0];
    const float* edge_attr= (const float*)d_in[1];
    const float* lin0_w   = (const float*)d_in[2];
    const float* lin0_b   = (const float*)d_in[3];
    const float* mlp1_w   = (const float*)d_in[4];
    const float* mlp1_b   = (const float*)d_in[5];
    const float* mlp2_w   = (const float*)d_in[6];
    const float* mlp2_b   = (const float*)d_in[7];
    const float* root_w   = (const float*)d_in[8];
    const float* conv_b   = (const float*)d_in[9];
    const float* bn       = (const float*)d_in[10];
    const float* gru_wih  = (const float*)d_in[11];
    const float* gru_whh  = (const float*)d_in[12];
    const float* gru_bih  = (const float*)d_in[13];
    const float* gru_bhh  = (const float*)d_in[14];
    const float* gc_rel_w = (const float*)d_in[15];
    const float* gc_rel_b = (const float*)d_in[16];
    const float* gc_root_w= (const float*)d_in[17];
    const float* bnl      = (const float*)d_in[18];
    const float* fc1_w    = (const float*)d_in[19];
    const float* fc1_b    = (const float*)d_in[20];
    const float* fcbn1    = (const float*)d_in[21];
    const float* fc2_w    = (const float*)d_in[22];
    const float* fc2_b    = (const float*)d_in[23];
    const float* fcbn2    = (const float*)d_in[24];
    const float* fcl_w    = (const float*)d_in[25];
    const float* fcl_b    = (const float*)d_in[26];
    const int*   ei       = (const int*)d_in[27];
    const int*   batch    = (const int*)d_in[28];
    float* out = (float*)d_out;

    cudaFuncSetAttribute(k_msg_mma, cudaFuncAttributeMaxDynamicSharedMemorySize, MSG_SMEM);

    // launch index 0..2 before k_msg_mma so ncu (-s 5, offset-2) captures the GEMM
    k_perm<<<2496, 256>>>(mlp2_w, mlp2_b, gru_wih, gru_whh,
                          gc_rel_w, gc_root_w, fc1_w, fc2_w);             // 0
    k_lin0<<<(NN * DD) / 256, 256>>>(x, lin0_w, lin0_b);                  // 1
    k_emlp<<<(EE * DD) / 256, 256>>>(edge_attr, mlp1_w, mlp1_b);          // 2 (+aggr zero)
    k_msg_mma<<<EE / MT, 256, MSG_SMEM>>>(0, ei);                         // 3  <- captured
    k_node<<<NN, 64>>>(0, root_w, conv_b, bn, gru_bih, gru_bhh);          // 4 (+aggr zero)

    k_emlp<<<(EE * DD) / 256, 256>>>(edge_attr, mlp1_w + 384, mlp1_b + 64);   // 5
    k_msg_mma<<<EE / MT, 256, MSG_SMEM>>>(1, ei);                             // 6
    k_node<<<NN, 64>>>(1, root_w + 4096, conv_b + 64, bn + 256,
                       gru_bih + 192, gru_bhh + 192);                         // 7 (+aggr zero)

    k_gcsc<<<(EE * DD) / 256, 256>>>(ei);                                 // 8 (+pooled zero)
    k_gconv<<<NN, 64>>>(gc_rel_b, bnl, batch);                            // 9
    k_head<<<GG, 256>>>(fc1_b, fcbn1, fc2_b, fcbn2, fcl_w, fcl_b, out);   // 10
}

// round 14
// speedup vs baseline: 8.9907x; 1.1862x over previous
#include <cuda_runtime.h>
#include <cuda_fp16.h>
#include <math.h>
#include <stdint.h>

#define NN 16384
#define EE 65536
#define DD 64
#define GG 512
#define BN_EPS 1e-5f
#define NCH 65           // 64 uv-chunks + 1 bias chunk
#define MT 128           // edges per block in mma kernel

// ---------------- scratch (no allocations allowed) ----------------
__device__ float  g_h[NN * DD];           // node features / GRU hidden
__device__ float  g_ef[EE * DD];          // edge MLP1 output
__device__ float  g_aggr[NN * DD];        // scatter-add target
__device__ float  g_pooled[GG * DD];      // global_add_pool
__device__ __half g_Wph[2 * NCH * 4096];  // fragment-permuted mlp2 weights+bias (fp16)
__device__ float  g_gruT[2 * 64 * 384];   // GRU weights transposed [l][i][ih/hh][gate][o]
__device__ float  g_gcT[2 * 64 * 64];     // GraphConv rel/root transposed [mat][i][o]
__device__ float  g_fc1T[64 * 256];       // fc1 transposed [i][t]
__device__ float  g_fc2T[256 * 128];      // fc2 transposed [i][t]

// ---------------- helpers ----------------
__device__ __forceinline__ uint32_t smem_u32(const void* p) {
    uint32_t a;
    asm("{ .reg .u64 t; cvta.to.shared.u64 t, %1; cvt.u32.u64 %0, t; }" : "=r"(a) : "l"(p));
    return a;
}
__device__ __forceinline__ uint32_t f2h2(float lo, float hi) {
    __half2 h = __floats2half2_rn(lo, hi);
    return *reinterpret_cast<uint32_t*>(&h);
}

// fp16 m16n8k16 MMA, fp32 accumulate, named float4 accumulator.
#define MMAH(C, a0, a1, a2, a3, b0, b1)                                         \
    asm volatile(                                                               \
        "mma.sync.aligned.m16n8k16.row.col.f32.f16.f16.f32 "                    \
        "{%0,%1,%2,%3}, {%4,%5,%6,%7}, {%8,%9}, {%0,%1,%2,%3};"                 \
        : "+f"(C.x), "+f"(C.y), "+f"(C.z), "+f"(C.w)                            \
        : "r"(a0), "r"(a1), "r"(a2), "r"(a3), "r"(b0), "r"(b1))

// B fragment (b0,b1 for k16) = one LDS.64 from fragment-ordered smem chunk.
#define MMA_NT(nt, C)                                                           \
    do {                                                                        \
        uint2 bb = *(const uint2*)(WB + ((s * 8 + (nt)) * 32 + lane) * 4);      \
        MMAH(C, a0, a1, a2, a3, bb.x, bb.y);                                    \
    } while (0)

#define RED_NT(nt, C)                                                           \
    do {                                                                        \
        asm volatile("red.global.add.v2.f32 [%0], {%1,%2};"                     \
                     :: "l"(plo + (nt) * 8), "f"(C.x), "f"(C.y) : "memory");    \
        asm volatile("red.global.add.v2.f32 [%0], {%1,%2};"                     \
                     :: "l"(phi + (nt) * 8), "f"(C.z), "f"(C.w) : "memory");    \
    } while (0)

// ---------------- prep: fragment-permute Wph (fp16) + transpose small weights ----
//  [0, 532480)          : Wph fp16 fragment order for m16n8k16
//  [532480, 581632)     : gruT  [l][i][half][gate][o]
//  [581632, 589824)     : gcT   [mat][i][o]
//  [589824, 606208)     : fc1T  [i][t]
//  [606208, 638976)     : fc2T  [i][t]
__global__ void k_perm(const float* __restrict__ w2, const float* __restrict__ b2,
                       const float* __restrict__ wih, const float* __restrict__ whh,
                       const float* __restrict__ relw, const float* __restrict__ rootw,
                       const float* __restrict__ fc1w, const float* __restrict__ fc2w) {
    int idx = blockIdx.x * blockDim.x + threadIdx.x;   // 638976 total
    if (idx < 532480) {
        int l = idx / (NCH * 4096);
        int r = idx % (NCH * 4096);
        int ch = r >> 12, q = r & 4095;
        // fp16 k16 fragment order: [s][nt][lane][j], j -> (k low bit, k +8 group)
        int j = q & 3, lane = (q >> 2) & 31, nt = (q >> 7) & 7, s = q >> 10;
        int gid = lane >> 2, tig = lane & 3;
        int k = s * 16 + 2 * tig + (j & 1) + ((j >> 1) << 3);
        int o = nt * 8 + gid;
        float val;
        if (ch < 64) val = w2[l * 262144 + (ch * 64 + o) * 64 + k];
        else         val = b2[l * 4096 + k * 64 + o];
        g_Wph[idx] = __float2half_rn(val);
    } else if (idx < 581632) {
        int r = idx - 532480;
        int l = r / 24576; r %= 24576;
        int i = r / 384, q = r % 384;
        int half = q / 192, gate = (q % 192) / 64, o = q & 63;
        const float* src = half ? whh : wih;
        g_gruT[idx - 532480] = src[l * 12288 + (gate * 64 + o) * 64 + i];
    } else if (idx < 589824) {
        int r = idx - 581632;
        int mat = r / 4096; r %= 4096;
        int i = r >> 6, o = r & 63;
        g_gcT[idx - 581632] = (mat ? rootw : relw)[o * 64 + i];
    } else if (idx < 606208) {
        int r = idx - 589824;
        int i = r >> 8, t = r & 255;
        g_fc1T[r] = fc1w[t * 64 + i];
    } else {
        int r = idx - 606208;
        int i = r >> 7, t = r & 127;
        g_fc2T[r] = fc2w[t * 256 + i];
    }
}

__global__ void k_lin0(const float* __restrict__ x, const float* __restrict__ w,
                       const float* __restrict__ b) {
    int idx = blockIdx.x * blockDim.x + threadIdx.x;
    int n = idx >> 6, o = idx & 63;
    float a = b[o];
#pragma unroll
    for (int f = 0; f < 16; f++) a += x[n * 16 + f] * w[o * 16 + f];
    g_h[idx] = fmaxf(a, 0.f);
}

// edge MLP1 + fused g_aggr zero
__global__ void k_emlp(const float* __restrict__ ea, const float* __restrict__ w,
                       const float* __restrict__ b) {
    int idx = blockIdx.x * blockDim.x + threadIdx.x;
    int e = idx >> 6, c = idx & 63;
    float a = b[c];
#pragma unroll
    for (int k = 0; k < 6; k++) a += ea[e * 6 + k] * w[c * 6 + k];
    g_ef[idx] = fmaxf(a, 0.f);
    if (idx < NN * DD) g_aggr[idx] = 0.f;
}

// ---------------- NNConv message GEMM via fp16 mma.sync m16n8k16 ----------------
// Block: 128 edges x 64 outputs, 8 warps (warp tile 16m x 64n), K = 65*64.
// A chunk (ch<64): A[m,c] = u[m,ch]*v[m,c] packed to fp16x2 in registers.
// Chunk 64 (bias): A[m,i] = u[m,i]. B chunks (8KB fp16) cp.async double-buffered.
#define UT_S 129
#define VS_S 68
#define OFF_VS (64 * UT_S)
#define OFF_WB (OFF_VS + MT * VS_S)               // float index where half buf starts
#define MSG_SMEM (OFF_WB * 4 + 2 * 4096 * 2)

__global__ void k_msg_mma(int l, const int* __restrict__ ei) {
    extern __shared__ float smf[];
    float* Ut = smf;                              // [i][m] u transposed
    float* Vs = smf + OFF_VS;                     // [m][c] edge features
    __half* Wbh = (__half*)(smf + OFF_WB);        // [2][4096] fp16 W double buffer
    const uint32_t wsm = smem_u32(Wbh);

    const __half* __restrict__ Wph = g_Wph + l * (NCH * 4096);

    const int t = threadIdx.x;
    const int wid = t >> 5, lane = t & 31;
    const int gid = lane >> 2, tig = lane & 3;
    const int e0 = blockIdx.x * MT;
    const int rl = wid * 16 + gid, rh = rl + 8;

    // Prefetch W chunk 0 (8KB = 512 x 16B, 2 per thread)
#pragma unroll
    for (int p = 0; p < 2; p++) {
        int i4 = t + p * 256;
        asm volatile("cp.async.cg.shared.global [%0], [%1], 16;"
                     :: "r"(wsm + i4 * 16), "l"(Wph + i4 * 8) : "memory");
    }
    asm volatile("cp.async.commit_group;" ::: "memory");

    // Stage U (transposed, gathered h rows) and V tiles.
#pragma unroll
    for (int p = 0; p < 8; p++) {
        int idx = t + p * 256;
        int m = idx >> 4, q = idx & 15;
        int s_ = ei[e0 + m];
        float4 u4 = *(const float4*)(g_h + (size_t)s_ * 64 + q * 4);
        Ut[(q * 4 + 0) * UT_S + m] = u4.x;
        Ut[(q * 4 + 1) * UT_S + m] = u4.y;
        Ut[(q * 4 + 2) * UT_S + m] = u4.z;
        Ut[(q * 4 + 3) * UT_S + m] = u4.w;
        float4 v4 = *(const float4*)(g_ef + (size_t)(e0 + m) * 64 + q * 4);
        *(float4*)(Vs + m * VS_S + q * 4) = v4;
    }

    float4 A0 = {0.f, 0.f, 0.f, 0.f}, A1 = A0, A2 = A0, A3 = A0;
    float4 A4 = A0, A5 = A0, A6 = A0, A7 = A0;

#pragma unroll 1
    for (int ch = 0; ch < 64; ch++) {
        asm volatile("cp.async.wait_group 0;" ::: "memory");
        __syncthreads();
        {   // prefetch next chunk (incl. bias chunk 64) into other buffer
            const __half* src = Wph + (ch + 1) * 4096;
            uint32_t dst = wsm + ((ch + 1) & 1) * 8192;
#pragma unroll
            for (int p = 0; p < 2; p++) {
                int i4 = t + p * 256;
                asm volatile("cp.async.cg.shared.global [%0], [%1], 16;"
                             :: "r"(dst + i4 * 16), "l"(src + i4 * 8) : "memory");
            }
            asm volatile("cp.async.commit_group;" ::: "memory");
        }
        const __half* WB = Wbh + (ch & 1) * 4096;
        const float ua = Ut[ch * UT_S + rl];
        const float ub = Ut[ch * UT_S + rh];
#pragma unroll
        for (int s = 0; s < 4; s++) {
            const int c0 = s * 16 + 2 * tig;
            float2 vl0 = *(const float2*)(Vs + rl * VS_S + c0);
            float2 vh0 = *(const float2*)(Vs + rh * VS_S + c0);
            float2 vl8 = *(const float2*)(Vs + rl * VS_S + c0 + 8);
            float2 vh8 = *(const float2*)(Vs + rh * VS_S + c0 + 8);
            uint32_t a0 = f2h2(ua * vl0.x, ua * vl0.y);
            uint32_t a1 = f2h2(ub * vh0.x, ub * vh0.y);
            uint32_t a2 = f2h2(ua * vl8.x, ua * vl8.y);
            uint32_t a3 = f2h2(ub * vh8.x, ub * vh8.y);
            MMA_NT(0, A0); MMA_NT(1, A1); MMA_NT(2, A2); MMA_NT(3, A3);
            MMA_NT(4, A4); MMA_NT(5, A5); MMA_NT(6, A6); MMA_NT(7, A7);
        }
    }

    // Bias chunk (64): A[m,i] = u[m,i]; chunk 64 -> buffer 0
    asm volatile("cp.async.wait_group 0;" ::: "memory");
    __syncthreads();
    {
        const __half* WB = Wbh;
#pragma unroll
        for (int s = 0; s < 4; s++) {
            const int c0 = s * 16 + 2 * tig;
            uint32_t a0 = f2h2(Ut[c0 * UT_S + rl], Ut[(c0 + 1) * UT_S + rl]);
            uint32_t a1 = f2h2(Ut[c0 * UT_S + rh], Ut[(c0 + 1) * UT_S + rh]);
            uint32_t a2 = f2h2(Ut[(c0 + 8) * UT_S + rl], Ut[(c0 + 9) * UT_S + rl]);
            uint32_t a3 = f2h2(Ut[(c0 + 8) * UT_S + rh], Ut[(c0 + 9) * UT_S + rh]);
            MMA_NT(0, A0); MMA_NT(1, A1); MMA_NT(2, A2); MMA_NT(3, A3);
            MMA_NT(4, A4); MMA_NT(5, A5); MMA_NT(6, A6); MMA_NT(7, A7);
        }
    }

    // Epilogue: scatter-add into aggr[dst] (C layout identical to tf32 path).
    {
        int dlo = ei[EE + e0 + rl];
        int dhi = ei[EE + e0 + rh];
        float* plo = g_aggr + (size_t)dlo * 64 + 2 * tig;
        float* phi = g_aggr + (size_t)dhi * 64 + 2 * tig;
        RED_NT(0, A0); RED_NT(1, A1); RED_NT(2, A2); RED_NT(3, A3);
        RED_NT(4, A4); RED_NT(5, A5); RED_NT(6, A6); RED_NT(7, A7);
    }
}

// ---------------- per-node: root + bias + relu + BN + GRU (coalesced weights) ----
__global__ void k_node(int l, const float* __restrict__ root_w,
                       const float* __restrict__ conv_b, const float* __restrict__ bn,
                       const float* __restrict__ bih, const float* __restrict__ bhh) {
    __shared__ float hrow[64], mrow[64];
    const float* __restrict__ gT = g_gruT + l * (64 * 384);
    int n = blockIdx.x, o = threadIdx.x;
    float hv = g_h[n * 64 + o];
    hrow[o] = hv;
    __syncthreads();
    float acc = g_aggr[n * 64 + o] + conv_b[o];
    g_aggr[n * 64 + o] = 0.f;     // fused zero for next aggregation
#pragma unroll 16
    for (int i = 0; i < 64; i++) acc += hrow[i] * root_w[i * 64 + o];
    acc = fmaxf(acc, 0.f);
    acc = (acc - bn[128 + o]) * rsqrtf(bn[192 + o] + BN_EPS) * bn[o] + bn[64 + o];
    mrow[o] = acc;
    __syncthreads();
    float gir = bih[o], giz = bih[64 + o], gin = bih[128 + o];
    float ghr = bhh[o], ghz = bhh[64 + o], ghn = bhh[128 + o];
#pragma unroll 8
    for (int i = 0; i < 64; i++) {
        float mi = mrow[i], hi = hrow[i];
        const float* gi = gT + i * 384;
        gir += mi * gi[o];
        giz += mi * gi[64 + o];
        gin += mi * gi[128 + o];
        ghr += hi * gi[192 + o];
        ghz += hi * gi[256 + o];
        ghn += hi * gi[320 + o];
    }
    float r = 1.f / (1.f + expf(-(gir + ghr)));
    float z = 1.f / (1.f + expf(-(giz + ghz)));
    float nv = tanhf(gin + r * ghn);
    g_h[n * 64 + o] = (1.f - z) * nv + z * hv;
}

// ---------------- GraphConv scatter + fused pooled zero ----------------
__global__ void k_gcsc(const int* __restrict__ ei) {
    int idx = blockIdx.x * blockDim.x + threadIdx.x;
    int e = idx >> 6, o = idx & 63;
    int s = ei[e], d = ei[EE + e];
    atomicAdd(&g_aggr[d * 64 + o], g_h[s * 64 + o]);
    if (idx < GG * DD) g_pooled[idx] = 0.f;
}

// ---------------- GraphConv linear + BN + pool scatter ----------------
__global__ void k_gconv(const float* __restrict__ relb, const float* __restrict__ bnl,
                        const int* __restrict__ batch) {
    __shared__ float arow[64], hrow[64];
    int n = blockIdx.x, o = threadIdx.x;
    arow[o] = g_aggr[n * 64 + o];
    hrow[o] = g_h[n * 64 + o];
    __syncthreads();
    float a = relb[o];
#pragma unroll 16
    for (int i = 0; i < 64; i++)
        a += arow[i] * g_gcT[i * 64 + o] + hrow[i] * g_gcT[4096 + i * 64 + o];
    a = fmaxf(a, 0.f);
    a = (a - bnl[128 + o]) * rsqrtf(bnl[192 + o] + BN_EPS) * bnl[o] + bnl[64 + o];
    atomicAdd(&g_pooled[batch[n] * 64 + o], a);
}

// ---------------- FC head ----------------
__global__ void k_head(const float* __restrict__ fc1_b, const float* __restrict__ fcbn1,
                       const float* __restrict__ fc2_b, const float* __restrict__ fcbn2,
                       const float* __restrict__ fcl_w, const float* __restrict__ fcl_b,
                       float* __restrict__ out) {
    __shared__ float prow[64], f1[256], f2[128], red[256];
    int g = blockIdx.x, t = threadIdx.x;
    if (t < 64) prow[t] = g_pooled[g * 64 + t];
    __syncthreads();
    {
        float a = fc1_b[t];
#pragma unroll 16
        for (int i = 0; i < 64; i++) a += prow[i] * g_fc1T[i * 256 + t];
        a = fmaxf(a, 0.f);
        a = (a - fcbn1[512 + t]) * rsqrtf(fcbn1[768 + t] + BN_EPS) * fcbn1[t] + fcbn1[256 + t];
        f1[t] = a;
    }
    __syncthreads();
    if (t < 128) {
        float a = fc2_b[t];
#pragma unroll 16
        for (int i = 0; i < 256; i++) a += f1[i] * g_fc2T[i * 128 + t];
        a = fmaxf(a, 0.f);
        a = (a - fcbn2[256 + t]) * rsqrtf(fcbn2[384 + t] + BN_EPS) * fcbn2[t] + fcbn2[128 + t];
        f2[t] = a;
    }
    __syncthreads();
    red[t] = (t < 128) ? f2[t] * fcl_w[t] : 0.f;
    __syncthreads();
    for (int s = 128; s > 0; s >>= 1) {
        if (t < s) red[t] += red[t + s];
        __syncthreads();
    }
    if (t == 0) out[g] = red[0] + fcl_b[0];
}

// ---------------- launcher ----------------
extern "C" void kernel_launch(void* const* d_in, const int* in_sizes, int n_in,
                              void* d_out, int out_size) {
    const float* x        = (const float*)d_in[0];
    const float* edge_attr= (const float*)d_in[1];
    const float* lin0_w   = (const float*)d_in[2];
    const float* lin0_b   = (const float*)d_in[3];
    const float* mlp1_w   = (const float*)d_in[4];
    const float* mlp1_b   = (const float*)d_in[5];
    const float* mlp2_w   = (const float*)d_in[6];
    const float* mlp2_b   = (const float*)d_in[7];
    const float* root_w   = (const float*)d_in[8];
    const float* conv_b   = (const float*)d_in[9];
    const float* bn       = (const float*)d_in[10];
    const float* gru_wih  = (const float*)d_in[11];
    const float* gru_whh  = (const float*)d_in[12];
    const float* gru_bih  = (const float*)d_in[13];
    const float* gru_bhh  = (const float*)d_in[14];
    const float* gc_rel_w = (const float*)d_in[15];
    const float* gc_rel_b = (const float*)d_in[16];
    const float* gc_root_w= (const float*)d_in[17];
    const float* bnl      = (const float*)d_in[18];
    const float* fc1_w    = (const float*)d_in[19];
    const float* fc1_b    = (const float*)d_in[20];
    const float* fcbn1    = (const float*)d_in[21];
    const float* fc2_w    = (const float*)d_in[22];
    const float* fc2_b    = (const float*)d_in[23];
    const float* fcbn2    = (const float*)d_in[24];
    const float* fcl_w    = (const float*)d_in[25];
    const float* fcl_b    = (const float*)d_in[26];
    const int*   ei       = (const int*)d_in[27];
    const int*   batch    = (const int*)d_in[28];
    float* out = (float*)d_out;

    cudaFuncSetAttribute(k_msg_mma, cudaFuncAttributeMaxDynamicSharedMemorySize, MSG_SMEM);

    k_perm<<<2496, 256>>>(mlp2_w, mlp2_b, gru_wih, gru_whh,
                          gc_rel_w, gc_root_w, fc1_w, fc2_w);             // 0
    k_lin0<<<(NN * DD) / 256, 256>>>(x, lin0_w, lin0_b);                  // 1
    k_emlp<<<(EE * DD) / 256, 256>>>(edge_attr, mlp1_w, mlp1_b);          // 2 (+aggr zero)
    k_msg_mma<<<EE / MT, 256, MSG_SMEM>>>(0, ei);                         // 3  <- captured
    k_node<<<NN, 64>>>(0, root_w, conv_b, bn, gru_bih, gru_bhh);          // 4 (+aggr zero)

    k_emlp<<<(EE * DD) / 256, 256>>>(edge_attr, mlp1_w + 384, mlp1_b + 64);   // 5
    k_msg_mma<<<EE / MT, 256, MSG_SMEM>>>(1, ei);                             // 6
    k_node<<<NN, 64>>>(1, root_w + 4096, conv_b + 64, bn + 256,
                       gru_bih + 192, gru_bhh + 192);                         // 7 (+aggr zero)

    k_gcsc<<<(EE * DD) / 256, 256>>>(ei);                                 // 8 (+pooled zero)
    k_gconv<<<NN, 64>>>(gc_rel_b, bnl, batch);                            // 9
    k_head<<<GG, 256>>>(fc1_b, fcbn1, fc2_b, fcbn2, fcl_w, fcl_b, out);   // 10
}

// round 15
// speedup vs baseline: 11.3183x; 1.2589x over previous
#include <cuda_runtime.h>
#include <cuda_fp16.h>
#include <math.h>
#include <stdint.h>

#define NN 16384
#define EE 65536
#define DD 64
#define GG 512
#define BN_EPS 1e-5f
#define NCH 65           // 64 uv-chunks + 1 bias chunk
#define MT 128           // edges per block in mma kernel

// ---------------- scratch (no allocations allowed) ----------------
__device__ float  g_h[NN * DD];           // node features / GRU hidden
__device__ float  g_ef[EE * DD];          // edge MLP1 output
__device__ float  g_aggr[NN * DD];        // scatter-add target
__device__ float  g_pooled[GG * DD];      // global_add_pool
__device__ __half g_Wph[2 * NCH * 4096];  // fragment-permuted mlp2 weights+bias (fp16)
__device__ float  g_gruT[2 * 64 * 384];   // GRU weights transposed [l][i][ih/hh][gate][o]
__device__ float  g_gcT[2 * 64 * 64];     // GraphConv rel/root transposed [mat][i][o]
__device__ float  g_fc1T[64 * 256];       // fc1 transposed [i][t]
__device__ float  g_fc2T[256 * 128];      // fc2 transposed [i][t]

// ---------------- helpers ----------------
__device__ __forceinline__ uint32_t smem_u32(const void* p) {
    uint32_t a;
    asm("{ .reg .u64 t; cvta.to.shared.u64 t, %1; cvt.u32.u64 %0, t; }" : "=r"(a) : "l"(p));
    return a;
}
__device__ __forceinline__ uint32_t h2u(__half2 h) {
    return *reinterpret_cast<uint32_t*>(&h);
}

// fp16 m16n8k16 MMA, fp32 accumulate, named float4 accumulator.
#define MMAH(C, a0, a1, a2, a3, b0, b1)                                         \
    asm volatile(                                                               \
        "mma.sync.aligned.m16n8k16.row.col.f32.f16.f16.f32 "                    \
        "{%0,%1,%2,%3}, {%4,%5,%6,%7}, {%8,%9}, {%0,%1,%2,%3};"                 \
        : "+f"(C.x), "+f"(C.y), "+f"(C.z), "+f"(C.w)                            \
        : "r"(a0), "r"(a1), "r"(a2), "r"(a3), "r"(b0), "r"(b1))

// B fragment (b0,b1 for k16) = one LDS.64 from fragment-ordered smem chunk.
#define MMA_NT(nt, C)                                                           \
    do {                                                                        \
        uint2 bb = *(const uint2*)(WB + ((s * 8 + (nt)) * 32 + lane) * 4);      \
        MMAH(C, a0, a1, a2, a3, bb.x, bb.y);                                    \
    } while (0)

// One k16 step: A fragments from register-resident V (chunk-invariant) * ua/ub.
#define MMA_S(sv, VL0, VH0, VL8, VH8)                                           \
    do {                                                                        \
        const int s = (sv);                                                     \
        uint32_t a0 = h2u(__hmul2(ua2, VL0));                                   \
        uint32_t a1 = h2u(__hmul2(ub2, VH0));                                   \
        uint32_t a2 = h2u(__hmul2(ua2, VL8));                                   \
        uint32_t a3 = h2u(__hmul2(ub2, VH8));                                   \
        MMA_NT(0, A0); MMA_NT(1, A1); MMA_NT(2, A2); MMA_NT(3, A3);             \
        MMA_NT(4, A4); MMA_NT(5, A5); MMA_NT(6, A6); MMA_NT(7, A7);             \
    } while (0)

#define RED_NT(nt, C)                                                           \
    do {                                                                        \
        asm volatile("red.global.add.v2.f32 [%0], {%1,%2};"                     \
                     :: "l"(plo + (nt) * 8), "f"(C.x), "f"(C.y) : "memory");    \
        asm volatile("red.global.add.v2.f32 [%0], {%1,%2};"                     \
                     :: "l"(phi + (nt) * 8), "f"(C.z), "f"(C.w) : "memory");    \
    } while (0)

// ---------------- prep: fragment-permute Wph (fp16) + transpose small weights ----
__global__ void k_perm(const float* __restrict__ w2, const float* __restrict__ b2,
                       const float* __restrict__ wih, const float* __restrict__ whh,
                       const float* __restrict__ relw, const float* __restrict__ rootw,
                       const float* __restrict__ fc1w, const float* __restrict__ fc2w) {
    int idx = blockIdx.x * blockDim.x + threadIdx.x;   // 638976 total
    if (idx < 532480) {
        int l = idx / (NCH * 4096);
        int r = idx % (NCH * 4096);
        int ch = r >> 12, q = r & 4095;
        int j = q & 3, lane = (q >> 2) & 31, nt = (q >> 7) & 7, s = q >> 10;
        int gid = lane >> 2, tig = lane & 3;
        int k = s * 16 + 2 * tig + (j & 1) + ((j >> 1) << 3);
        int o = nt * 8 + gid;
        float val;
        if (ch < 64) val = w2[l * 262144 + (ch * 64 + o) * 64 + k];
        else         val = b2[l * 4096 + k * 64 + o];
        g_Wph[idx] = __float2half_rn(val);
    } else if (idx < 581632) {
        int r = idx - 532480;
        int l = r / 24576; r %= 24576;
        int i = r / 384, q = r % 384;
        int half = q / 192, gate = (q % 192) / 64, o = q & 63;
        const float* src = half ? whh : wih;
        g_gruT[idx - 532480] = src[l * 12288 + (gate * 64 + o) * 64 + i];
    } else if (idx < 589824) {
        int r = idx - 581632;
        int mat = r / 4096; r %= 4096;
        int i = r >> 6, o = r & 63;
        g_gcT[idx - 581632] = (mat ? rootw : relw)[o * 64 + i];
    } else if (idx < 606208) {
        int r = idx - 589824;
        int i = r >> 8, t = r & 255;
        g_fc1T[r] = fc1w[t * 64 + i];
    } else {
        int r = idx - 606208;
        int i = r >> 7, t = r & 127;
        g_fc2T[r] = fc2w[t * 256 + i];
    }
}

__global__ void k_lin0(const float* __restrict__ x, const float* __restrict__ w,
                       const float* __restrict__ b) {
    int idx = blockIdx.x * blockDim.x + threadIdx.x;
    int n = idx >> 6, o = idx & 63;
    float a = b[o];
#pragma unroll
    for (int f = 0; f < 16; f++) a += x[n * 16 + f] * w[o * 16 + f];
    g_h[idx] = fmaxf(a, 0.f);
}

// edge MLP1 + fused g_aggr zero
__global__ void k_emlp(const float* __restrict__ ea, const float* __restrict__ w,
                       const float* __restrict__ b) {
    int idx = blockIdx.x * blockDim.x + threadIdx.x;
    int e = idx >> 6, c = idx & 63;
    float a = b[c];
#pragma unroll
    for (int k = 0; k < 6; k++) a += ea[e * 6 + k] * w[c * 6 + k];
    g_ef[idx] = fmaxf(a, 0.f);
    if (idx < NN * DD) g_aggr[idx] = 0.f;
}

// ---------------- NNConv message GEMM via fp16 mma.sync m16n8k16 ----------------
// Block: 128 edges x 64 outputs, 8 warps (warp tile 16m x 64n), K = 65*64.
// V values are chunk-invariant -> held in 16 named half2 REGISTERS (no Vs smem).
// A chunk (ch<64): A[m,c] = u[m,ch]*v[m,c] via HMUL2. Chunk 64 (bias): A = u.
// SMEM: Ut[64][129] fp32 (33KB) + Wbh[2][4096] fp16 (16KB) = 49.4KB.
#define UT_S 129
#define OFF_WB (64 * UT_S)                        // float index where half buf starts
#define MSG_SMEM (OFF_WB * 4 + 2 * 4096 * 2)

__global__ void k_msg_mma(int l, const int* __restrict__ ei) {
    extern __shared__ float smf[];
    float* Ut = smf;                              // [i][m] u transposed
    __half* Wbh = (__half*)(smf + OFF_WB);        // [2][4096] fp16 W double buffer
    const uint32_t wsm = smem_u32(Wbh);

    const __half* __restrict__ Wph = g_Wph + l * (NCH * 4096);

    const int t = threadIdx.x;
    const int wid = t >> 5, lane = t & 31;
    const int gid = lane >> 2, tig = lane & 3;
    const int e0 = blockIdx.x * MT;
    const int rl = wid * 16 + gid, rh = rl + 8;

    // Prefetch W chunk 0 (8KB = 512 x 16B, 2 per thread)
#pragma unroll
    for (int p = 0; p < 2; p++) {
        int i4 = t + p * 256;
        asm volatile("cp.async.cg.shared.global [%0], [%1], 16;"
                     :: "r"(wsm + i4 * 16), "l"(Wph + i4 * 8) : "memory");
    }
    asm volatile("cp.async.commit_group;" ::: "memory");

    // Stage U (transposed, gathered h rows) into smem.
#pragma unroll
    for (int p = 0; p < 8; p++) {
        int idx = t + p * 256;
        int m = idx >> 4, q = idx & 15;
        int s_ = ei[e0 + m];
        float4 u4 = *(const float4*)(g_h + (size_t)s_ * 64 + q * 4);
        Ut[(q * 4 + 0) * UT_S + m] = u4.x;
        Ut[(q * 4 + 1) * UT_S + m] = u4.y;
        Ut[(q * 4 + 2) * UT_S + m] = u4.z;
        Ut[(q * 4 + 3) * UT_S + m] = u4.w;
    }

    // Load this thread's V values straight from gmem -> 16 half2 registers.
    const float* vl = g_ef + (size_t)(e0 + rl) * 64 + 2 * tig;
    const float* vh = g_ef + (size_t)(e0 + rh) * 64 + 2 * tig;
#define LDV(p) __floats2half2_rn((p).x, (p).y)
    float2 p0, p1;
    p0 = *(const float2*)(vl +  0); p1 = *(const float2*)(vl +  8);
    __half2 V0L0 = LDV(p0), V0L8 = LDV(p1);
    p0 = *(const float2*)(vh +  0); p1 = *(const float2*)(vh +  8);
    __half2 V0H0 = LDV(p0), V0H8 = LDV(p1);
    p0 = *(const float2*)(vl + 16); p1 = *(const float2*)(vl + 24);
    __half2 V1L0 = LDV(p0), V1L8 = LDV(p1);
    p0 = *(const float2*)(vh + 16); p1 = *(const float2*)(vh + 24);
    __half2 V1H0 = LDV(p0), V1H8 = LDV(p1);
    p0 = *(const float2*)(vl + 32); p1 = *(const float2*)(vl + 40);
    __half2 V2L0 = LDV(p0), V2L8 = LDV(p1);
    p0 = *(const float2*)(vh + 32); p1 = *(const float2*)(vh + 40);
    __half2 V2H0 = LDV(p0), V2H8 = LDV(p1);
    p0 = *(const float2*)(vl + 48); p1 = *(const float2*)(vl + 56);
    __half2 V3L0 = LDV(p0), V3L8 = LDV(p1);
    p0 = *(const float2*)(vh + 48); p1 = *(const float2*)(vh + 56);
    __half2 V3H0 = LDV(p0), V3H8 = LDV(p1);
#undef LDV

    float4 A0 = {0.f, 0.f, 0.f, 0.f}, A1 = A0, A2 = A0, A3 = A0;
    float4 A4 = A0, A5 = A0, A6 = A0, A7 = A0;

#pragma unroll 1
    for (int ch = 0; ch < 64; ch++) {
        asm volatile("cp.async.wait_group 0;" ::: "memory");
        __syncthreads();
        {   // prefetch next chunk (incl. bias chunk 64) into other buffer
            const __half* src = Wph + (ch + 1) * 4096;
            uint32_t dst = wsm + ((ch + 1) & 1) * 8192;
#pragma unroll
            for (int p = 0; p < 2; p++) {
                int i4 = t + p * 256;
                asm volatile("cp.async.cg.shared.global [%0], [%1], 16;"
                             :: "r"(dst + i4 * 16), "l"(src + i4 * 8) : "memory");
            }
            asm volatile("cp.async.commit_group;" ::: "memory");
        }
        const __half* WB = Wbh + (ch & 1) * 4096;
        const __half2 ua2 = __float2half2_rn(Ut[ch * UT_S + rl]);
        const __half2 ub2 = __float2half2_rn(Ut[ch * UT_S + rh]);
        MMA_S(0, V0L0, V0H0, V0L8, V0H8);
        MMA_S(1, V1L0, V1H0, V1L8, V1H8);
        MMA_S(2, V2L0, V2H0, V2L8, V2H8);
        MMA_S(3, V3L0, V3H0, V3L8, V3H8);
    }

    // Bias chunk (64): A[m,i] = u[m,i]; chunk 64 -> buffer 0
    asm volatile("cp.async.wait_group 0;" ::: "memory");
    __syncthreads();
    {
        const __half* WB = Wbh;
#pragma unroll
        for (int s = 0; s < 4; s++) {
            const int c0 = s * 16 + 2 * tig;
            uint32_t a0 = h2u(__floats2half2_rn(Ut[c0 * UT_S + rl], Ut[(c0 + 1) * UT_S + rl]));
            uint32_t a1 = h2u(__floats2half2_rn(Ut[c0 * UT_S + rh], Ut[(c0 + 1) * UT_S + rh]));
            uint32_t a2 = h2u(__floats2half2_rn(Ut[(c0 + 8) * UT_S + rl], Ut[(c0 + 9) * UT_S + rl]));
            uint32_t a3 = h2u(__floats2half2_rn(Ut[(c0 + 8) * UT_S + rh], Ut[(c0 + 9) * UT_S + rh]));
            MMA_NT(0, A0); MMA_NT(1, A1); MMA_NT(2, A2); MMA_NT(3, A3);
            MMA_NT(4, A4); MMA_NT(5, A5); MMA_NT(6, A6); MMA_NT(7, A7);
        }
    }

    // Epilogue: scatter-add into aggr[dst].
    {
        int dlo = ei[EE + e0 + rl];
        int dhi = ei[EE + e0 + rh];
        float* plo = g_aggr + (size_t)dlo * 64 + 2 * tig;
        float* phi = g_aggr + (size_t)dhi * 64 + 2 * tig;
        RED_NT(0, A0); RED_NT(1, A1); RED_NT(2, A2); RED_NT(3, A3);
        RED_NT(4, A4); RED_NT(5, A5); RED_NT(6, A6); RED_NT(7, A7);
    }
}

// ---------------- per-node: root + bias + relu + BN + GRU (coalesced weights) ----
__global__ void k_node(int l, const float* __restrict__ root_w,
                       const float* __restrict__ conv_b, const float* __restrict__ bn,
                       const float* __restrict__ bih, const float* __restrict__ bhh) {
    __shared__ float hrow[64], mrow[64];
    const float* __restrict__ gT = g_gruT + l * (64 * 384);
    int n = blockIdx.x, o = threadIdx.x;
    float hv = g_h[n * 64 + o];
    hrow[o] = hv;
    __syncthreads();
    float acc = g_aggr[n * 64 + o] + conv_b[o];
    g_aggr[n * 64 + o] = 0.f;     // fused zero for next aggregation
#pragma unroll 16
    for (int i = 0; i < 64; i++) acc += hrow[i] * root_w[i * 64 + o];
    acc = fmaxf(acc, 0.f);
    acc = (acc - bn[128 + o]) * rsqrtf(bn[192 + o] + BN_EPS) * bn[o] + bn[64 + o];
    mrow[o] = acc;
    __syncthreads();
    float gir = bih[o], giz = bih[64 + o], gin = bih[128 + o];
    float ghr = bhh[o], ghz = bhh[64 + o], ghn = bhh[128 + o];
#pragma unroll 8
    for (int i = 0; i < 64; i++) {
        float mi = mrow[i], hi = hrow[i];
        const float* gi = gT + i * 384;
        gir += mi * gi[o];
        giz += mi * gi[64 + o];
        gin += mi * gi[128 + o];
        ghr += hi * gi[192 + o];
        ghz += hi * gi[256 + o];
        ghn += hi * gi[320 + o];
    }
    float r = 1.f / (1.f + expf(-(gir + ghr)));
    float z = 1.f / (1.f + expf(-(giz + ghz)));
    float nv = tanhf(gin + r * ghn);
    g_h[n * 64 + o] = (1.f - z) * nv + z * hv;
}

// ---------------- GraphConv scatter + fused pooled zero ----------------
__global__ void k_gcsc(const int* __restrict__ ei) {
    int idx = blockIdx.x * blockDim.x + threadIdx.x;
    int e = idx >> 6, o = idx & 63;
    int s = ei[e], d = ei[EE + e];
    atomicAdd(&g_aggr[d * 64 + o], g_h[s * 64 + o]);
    if (idx < GG * DD) g_pooled[idx] = 0.f;
}

// ---------------- GraphConv linear + BN + pool scatter ----------------
__global__ void k_gconv(const float* __restrict__ relb, const float* __restrict__ bnl,
                        const int* __restrict__ batch) {
    __shared__ float arow[64], hrow[64];
    int n = blockIdx.x, o = threadIdx.x;
    arow[o] = g_aggr[n * 64 + o];
    hrow[o] = g_h[n * 64 + o];
    __syncthreads();
    float a = relb[o];
#pragma unroll 16
    for (int i = 0; i < 64; i++)
        a += arow[i] * g_gcT[i * 64 + o] + hrow[i] * g_gcT[4096 + i * 64 + o];
    a = fmaxf(a, 0.f);
    a = (a - bnl[128 + o]) * rsqrtf(bnl[192 + o] + BN_EPS) * bnl[o] + bnl[64 + o];
    atomicAdd(&g_pooled[batch[n] * 64 + o], a);
}

// ---------------- FC head ----------------
__global__ void k_head(const float* __restrict__ fc1_b, const float* __restrict__ fcbn1,
                       const float* __restrict__ fc2_b, const float* __restrict__ fcbn2,
                       const float* __restrict__ fcl_w, const float* __restrict__ fcl_b,
                       float* __restrict__ out) {
    __shared__ float prow[64], f1[256], f2[128], red[256];
    int g = blockIdx.x, t = threadIdx.x;
    if (t < 64) prow[t] = g_pooled[g * 64 + t];
    __syncthreads();
    {
        float a = fc1_b[t];
#pragma unroll 16
        for (int i = 0; i < 64; i++) a += prow[i] * g_fc1T[i * 256 + t];
        a = fmaxf(a, 0.f);
        a = (a - fcbn1[512 + t]) * rsqrtf(fcbn1[768 + t] + BN_EPS) * fcbn1[t] + fcbn1[256 + t];
        f1[t] = a;
    }
    __syncthreads();
    if (t < 128) {
        float a = fc2_b[t];
#pragma unroll 16
        for (int i = 0; i < 256; i++) a += f1[i] * g_fc2T[i * 128 + t];
        a = fmaxf(a, 0.f);
        a = (a - fcbn2[256 + t]) * rsqrtf(fcbn2[384 + t] + BN_EPS) * fcbn2[t] + fcbn2[128 + t];
        f2[t] = a;
    }
    __syncthreads();
    red[t] = (t < 128) ? f2[t] * fcl_w[t] : 0.f;
    __syncthreads();
    for (int s = 128; s > 0; s >>= 1) {
        if (t < s) red[t] += red[t + s];
        __syncthreads();
    }
    if (t == 0) out[g] = red[0] + fcl_b[0];
}

// ---------------- launcher ----------------
extern "C" void kernel_launch(void* const* d_in, const int* in_sizes, int n_in,
                              void* d_out, int out_size) {
    const float* x        = (const float*)d_in[0];
    const float* edge_attr= (const float*)d_in[1];
    const float* lin0_w   = (const float*)d_in[2];
    const float* lin0_b   = (const float*)d_in[3];
    const float* mlp1_w   = (const float*)d_in[4];
    const float* mlp1_b   = (const float*)d_in[5];
    const float* mlp2_w   = (const float*)d_in[6];
    const float* mlp2_b   = (const float*)d_in[7];
    const float* root_w   = (const float*)d_in[8];
    const float* conv_b   = (const float*)d_in[9];
    const float* bn       = (const float*)d_in[10];
    const float* gru_wih  = (const float*)d_in[11];
    const float* gru_whh  = (const float*)d_in[12];
    const float* gru_bih  = (const float*)d_in[13];
    const float* gru_bhh  = (const float*)d_in[14];
    const float* gc_rel_w = (const float*)d_in[15];
    const float* gc_rel_b = (const float*)d_in[16];
    const float* gc_root_w= (const float*)d_in[17];
    const float* bnl      = (const float*)d_in[18];
    const float* fc1_w    = (const float*)d_in[19];
    const float* fc1_b    = (const float*)d_in[20];
    const float* fcbn1    = (const float*)d_in[21];
    const float* fc2_w    = (const float*)d_in[22];
    const float* fc2_b    = (const float*)d_in[23];
    const float* fcbn2    = (const float*)d_in[24];
    const float* fcl_w    = (const float*)d_in[25];
    const float* fcl_b    = (const float*)d_in[26];
    const int*   ei       = (const int*)d_in[27];
    const int*   batch    = (const int*)d_in[28];
    float* out = (float*)d_out;

    cudaFuncSetAttribute(k_msg_mma, cudaFuncAttributeMaxDynamicSharedMemorySize, MSG_SMEM);

    k_perm<<<2496, 256>>>(mlp2_w, mlp2_b, gru_wih, gru_whh,
                          gc_rel_w, gc_root_w, fc1_w, fc2_w);             // 0
    k_lin0<<<(NN * DD) / 256, 256>>>(x, lin0_w, lin0_b);                  // 1
    k_emlp<<<(EE * DD) / 256, 256>>>(edge_attr, mlp1_w, mlp1_b);          // 2 (+aggr zero)
    k_msg_mma<<<EE / MT, 256, MSG_SMEM>>>(0, ei);                         // 3  <- captured
    k_node<<<NN, 64>>>(0, root_w, conv_b, bn, gru_bih, gru_bhh);          // 4 (+aggr zero)

    k_emlp<<<(EE * DD) / 256, 256>>>(edge_attr, mlp1_w + 384, mlp1_b + 64);   // 5
    k_msg_mma<<<EE / MT, 256, MSG_SMEM>>>(1, ei);                             // 6
    k_node<<<NN, 64>>>(1, root_w + 4096, conv_b + 64, bn + 256,
                       gru_bih + 192, gru_bhh + 192);                         // 7 (+aggr zero)

    k_gcsc<<<(EE * DD) / 256, 256>>>(ei);                                 // 8 (+pooled zero)
    k_gconv<<<NN, 64>>>(gc_rel_b, bnl, batch);                            // 9
    k_head<<<GG, 256>>>(fc1_b, fcbn1, fc2_b, fcbn2, fcl_w, fcl_b, out);   // 10
}

// round 17
// speedup vs baseline: 11.5887x; 1.0239x over previous
#include <cuda_runtime.h>
#include <cuda_fp16.h>
#include <math.h>
#include <stdint.h>

#define NN 16384
#define EE 65536
#define DD 64
#define GG 512
#define BN_EPS 1e-5f
#define NCH 65           // 64 uv-chunks + 1 bias chunk
#define MT 128           // edges per block in mma kernel

// ---------------- scratch (no allocations allowed) ----------------
__device__ float  g_h[NN * DD];           // node features / GRU hidden
__device__ float  g_aggr[NN * DD];        // scatter-add target
__device__ float  g_pooled[GG * DD];      // global_add_pool
__device__ __half g_Wph[2 * NCH * 4096];  // fragment-permuted mlp2 weights+bias (fp16)
__device__ float  g_gruT[2 * 64 * 384];   // GRU weights transposed [l][i][ih/hh][gate][o]
__device__ float  g_gcT[2 * 64 * 64];     // GraphConv rel/root transposed [mat][i][o]
__device__ float  g_fc1T[64 * 256];       // fc1 transposed [i][t]
__device__ float  g_fc2T[256 * 128];      // fc2 transposed [i][t]

// ---------------- helpers ----------------
__device__ __forceinline__ uint32_t smem_u32(const void* p) {
    uint32_t a;
    asm("{ .reg .u64 t; cvta.to.shared.u64 t, %1; cvt.u32.u64 %0, t; }" : "=r"(a) : "l"(p));
    return a;
}
__device__ __forceinline__ uint32_t h2u(__half2 h) {
    return *reinterpret_cast<uint32_t*>(&h);
}
// edge-MLP pair: relu(b + a.ws) for columns (c, c+1), packed to half2
__device__ __forceinline__ __half2 efpair(const float* ws, float a0, float a1, float a2,
                                          float a3, float a4, float a5, int c) {
    const float* w0 = ws + c * 6;
    const float* w1 = ws + (c + 1) * 6;
    float x = ws[384 + c]     + a0 * w0[0] + a1 * w0[1] + a2 * w0[2] + a3 * w0[3] + a4 * w0[4] + a5 * w0[5];
    float y = ws[384 + c + 1] + a0 * w1[0] + a1 * w1[1] + a2 * w1[2] + a3 * w1[3] + a4 * w1[4] + a5 * w1[5];
    return __floats2half2_rn(fmaxf(x, 0.f), fmaxf(y, 0.f));
}

// fp16 m16n8k16 MMA, fp32 accumulate, named float4 accumulator.
#define MMAH(C, a0, a1, a2, a3, b0, b1)                                         \
    asm volatile(                                                               \
        "mma.sync.aligned.m16n8k16.row.col.f32.f16.f16.f32 "                    \
        "{%0,%1,%2,%3}, {%4,%5,%6,%7}, {%8,%9}, {%0,%1,%2,%3};"                 \
        : "+f"(C.x), "+f"(C.y), "+f"(C.z), "+f"(C.w)                            \
        : "r"(a0), "r"(a1), "r"(a2), "r"(a3), "r"(b0), "r"(b1))

#define MMA_NT(nt, C)                                                           \
    do {                                                                        \
        uint2 bb = *(const uint2*)(WB + ((s * 8 + (nt)) * 32 + lane) * 4);      \
        MMAH(C, a0, a1, a2, a3, bb.x, bb.y);                                    \
    } while (0)

#define MMA_S(sv, VL0, VH0, VL8, VH8)                                           \
    do {                                                                        \
        const int s = (sv);                                                     \
        uint32_t a0 = h2u(__hmul2(ua2, VL0));                                   \
        uint32_t a1 = h2u(__hmul2(ub2, VH0));                                   \
        uint32_t a2 = h2u(__hmul2(ua2, VL8));                                   \
        uint32_t a3 = h2u(__hmul2(ub2, VH8));                                   \
        MMA_NT(0, A0); MMA_NT(1, A1); MMA_NT(2, A2); MMA_NT(3, A3);             \
        MMA_NT(4, A4); MMA_NT(5, A5); MMA_NT(6, A6); MMA_NT(7, A7);             \
    } while (0)

#define RED_NT(nt, C)                                                           \
    do {                                                                        \
        asm volatile("red.global.add.v2.f32 [%0], {%1,%2};"                     \
                     :: "l"(plo + (nt) * 8), "f"(C.x), "f"(C.y) : "memory");    \
        asm volatile("red.global.add.v2.f32 [%0], {%1,%2};"                     \
                     :: "l"(phi + (nt) * 8), "f"(C.z), "f"(C.w) : "memory");    \
    } while (0)

// ---------------- prep: fragment-permute Wph (fp16) + transpose small weights ----
__global__ void k_perm(const float* __restrict__ w2, const float* __restrict__ b2,
                       const float* __restrict__ wih, const float* __restrict__ whh,
                       const float* __restrict__ relw, const float* __restrict__ rootw,
                       const float* __restrict__ fc1w, const float* __restrict__ fc2w) {
    int idx = blockIdx.x * blockDim.x + threadIdx.x;   // 638976 total
    if (idx < 532480) {
        int l = idx / (NCH * 4096);
        int r = idx % (NCH * 4096);
        int ch = r >> 12, q = r & 4095;
        int j = q & 3, lane = (q >> 2) & 31, nt = (q >> 7) & 7, s = q >> 10;
        int gid = lane >> 2, tig = lane & 3;
        int k = s * 16 + 2 * tig + (j & 1) + ((j >> 1) << 3);
        int o = nt * 8 + gid;
        float val;
        if (ch < 64) val = w2[l * 262144 + (ch * 64 + o) * 64 + k];
        else         val = b2[l * 4096 + k * 64 + o];
        g_Wph[idx] = __float2half_rn(val);
    } else if (idx < 581632) {
        int r = idx - 532480;
        int l = r / 24576; r %= 24576;
        int i = r / 384, q = r % 384;
        int half = q / 192, gate = (q % 192) / 64, o = q & 63;
        const float* src = half ? whh : wih;
        g_gruT[idx - 532480] = src[l * 12288 + (gate * 64 + o) * 64 + i];
    } else if (idx < 589824) {
        int r = idx - 581632;
        int mat = r / 4096; r %= 4096;
        int i = r >> 6, o = r & 63;
        g_gcT[idx - 581632] = (mat ? rootw : relw)[o * 64 + i];
    } else if (idx < 606208) {
        int r = idx - 589824;
        int i = r >> 8, t = r & 255;
        g_fc1T[r] = fc1w[t * 64 + i];
    } else {
        int r = idx - 606208;
        int i = r >> 7, t = r & 127;
        g_fc2T[r] = fc2w[t * 256 + i];
    }
}

// lin0 + fused g_aggr zero (same index range)
__global__ void k_lin0(const float* __restrict__ x, const float* __restrict__ w,
                       const float* __restrict__ b) {
    int idx = blockIdx.x * blockDim.x + threadIdx.x;
    int n = idx >> 6, o = idx & 63;
    float a = b[o];
#pragma unroll
    for (int f = 0; f < 16; f++) a += x[n * 16 + f] * w[o * 16 + f];
    g_h[idx] = fmaxf(a, 0.f);
    g_aggr[idx] = 0.f;
}

// ---------------- NNConv message GEMM, fp16 m16n8k16, fused edge-MLP ----------------
// Block: 128 edges x 64 outputs, 8 warps (16m x 64n). K = 65*64.
// V built IN REGISTERS from edge_attr via fused MLP1 (no g_ef at all).
// SMEM: Ut[64][129] fp32 | ws[448] mlp1 w+b | Wbh[2][4096] fp16.
#define UT_S 129
#define OFF_WS (64 * UT_S)
#define OFF_WB (OFF_WS + 448)
#define MSG_SMEM (OFF_WB * 4 + 2 * 4096 * 2)

__global__ void k_msg_mma(int l, const int* __restrict__ ei,
                          const float* __restrict__ mlp1w, const float* __restrict__ mlp1b,
                          const float* __restrict__ ea) {
    extern __shared__ float smf[];
    float* Ut = smf;                              // [i][m] u transposed
    float* ws = smf + OFF_WS;                     // mlp1 w (384) + b (64)
    __half* Wbh = (__half*)(smf + OFF_WB);        // [2][4096] fp16 W double buffer
    const uint32_t wsm = smem_u32(Wbh);

    const __half* __restrict__ Wph = g_Wph + l * (NCH * 4096);

    const int t = threadIdx.x;
    const int wid = t >> 5, lane = t & 31;
    const int gid = lane >> 2, tig = lane & 3;
    const int e0 = blockIdx.x * MT;
    const int rl = wid * 16 + gid, rh = rl + 8;

    // Prefetch W chunk 0
#pragma unroll
    for (int p = 0; p < 2; p++) {
        int i4 = t + p * 256;
        asm volatile("cp.async.cg.shared.global [%0], [%1], 16;"
                     :: "r"(wsm + i4 * 16), "l"(Wph + i4 * 8) : "memory");
    }
    asm volatile("cp.async.commit_group;" ::: "memory");

    // Stage mlp1 weights+bias into smem (448 entries, 256 threads -> strided!).
    for (int i = t; i < 448; i += 256)
        ws[i] = (i < 384) ? mlp1w[l * 384 + i] : mlp1b[l * 64 + i - 384];

    // Stage U (transposed, gathered h rows) into smem.
#pragma unroll
    for (int p = 0; p < 8; p++) {
        int idx = t + p * 256;
        int m = idx >> 4, q = idx & 15;
        int s_ = ei[e0 + m];
        float4 u4 = *(const float4*)(g_h + (size_t)s_ * 64 + q * 4);
        Ut[(q * 4 + 0) * UT_S + m] = u4.x;
        Ut[(q * 4 + 1) * UT_S + m] = u4.y;
        Ut[(q * 4 + 2) * UT_S + m] = u4.z;
        Ut[(q * 4 + 3) * UT_S + m] = u4.w;
    }
    __syncthreads();

    // Fused edge MLP: compute this thread's 16 V values into half2 registers.
    float2 e0a = *(const float2*)(ea + (size_t)(e0 + rl) * 6);
    float2 e1a = *(const float2*)(ea + (size_t)(e0 + rl) * 6 + 2);
    float2 e2a = *(const float2*)(ea + (size_t)(e0 + rl) * 6 + 4);
    float2 e0b = *(const float2*)(ea + (size_t)(e0 + rh) * 6);
    float2 e1b = *(const float2*)(ea + (size_t)(e0 + rh) * 6 + 2);
    float2 e2b = *(const float2*)(ea + (size_t)(e0 + rh) * 6 + 4);
    const int c0 = 2 * tig;
#define EFL(c) efpair(ws, e0a.x, e0a.y, e1a.x, e1a.y, e2a.x, e2a.y, (c))
#define EFH(c) efpair(ws, e0b.x, e0b.y, e1b.x, e1b.y, e2b.x, e2b.y, (c))
    __half2 V0L0 = EFL(c0),      V0L8 = EFL(c0 + 8);
    __half2 V0H0 = EFH(c0),      V0H8 = EFH(c0 + 8);
    __half2 V1L0 = EFL(c0 + 16), V1L8 = EFL(c0 + 24);
    __half2 V1H0 = EFH(c0 + 16), V1H8 = EFH(c0 + 24);
    __half2 V2L0 = EFL(c0 + 32), V2L8 = EFL(c0 + 40);
    __half2 V2H0 = EFH(c0 + 32), V2H8 = EFH(c0 + 40);
    __half2 V3L0 = EFL(c0 + 48), V3L8 = EFL(c0 + 56);
    __half2 V3H0 = EFH(c0 + 48), V3H8 = EFH(c0 + 56);
#undef EFL
#undef EFH

    float4 A0 = {0.f, 0.f, 0.f, 0.f}, A1 = A0, A2 = A0, A3 = A0;
    float4 A4 = A0, A5 = A0, A6 = A0, A7 = A0;

#pragma unroll 1
    for (int ch = 0; ch < 64; ch++) {
        asm volatile("cp.async.wait_group 0;" ::: "memory");
        __syncthreads();
        {   // prefetch next chunk (incl. bias chunk 64) into other buffer
            const __half* src = Wph + (ch + 1) * 4096;
            uint32_t dst = wsm + ((ch + 1) & 1) * 8192;
#pragma unroll
            for (int p = 0; p < 2; p++) {
                int i4 = t + p * 256;
                asm volatile("cp.async.cg.shared.global [%0], [%1], 16;"
                             :: "r"(dst + i4 * 16), "l"(src + i4 * 8) : "memory");
            }
            asm volatile("cp.async.commit_group;" ::: "memory");
        }
        const __half* WB = Wbh + (ch & 1) * 4096;
        const __half2 ua2 = __float2half2_rn(Ut[ch * UT_S + rl]);
        const __half2 ub2 = __float2half2_rn(Ut[ch * UT_S + rh]);
        MMA_S(0, V0L0, V0H0, V0L8, V0H8);
        MMA_S(1, V1L0, V1H0, V1L8, V1H8);
        MMA_S(2, V2L0, V2H0, V2L8, V2H8);
        MMA_S(3, V3L0, V3H0, V3L8, V3H8);
    }

    // Bias chunk (64): A[m,i] = u[m,i]; chunk 64 -> buffer 0
    asm volatile("cp.async.wait_group 0;" ::: "memory");
    __syncthreads();
    {
        const __half* WB = Wbh;
#pragma unroll
        for (int s = 0; s < 4; s++) {
            const int cc = s * 16 + 2 * tig;
            uint32_t a0 = h2u(__floats2half2_rn(Ut[cc * UT_S + rl], Ut[(cc + 1) * UT_S + rl]));
            uint32_t a1 = h2u(__floats2half2_rn(Ut[cc * UT_S + rh], Ut[(cc + 1) * UT_S + rh]));
            uint32_t a2 = h2u(__floats2half2_rn(Ut[(cc + 8) * UT_S + rl], Ut[(cc + 9) * UT_S + rl]));
            uint32_t a3 = h2u(__floats2half2_rn(Ut[(cc + 8) * UT_S + rh], Ut[(cc + 9) * UT_S + rh]));
            MMA_NT(0, A0); MMA_NT(1, A1); MMA_NT(2, A2); MMA_NT(3, A3);
            MMA_NT(4, A4); MMA_NT(5, A5); MMA_NT(6, A6); MMA_NT(7, A7);
        }
    }

    // Epilogue: scatter-add into aggr[dst].
    {
        int dlo = ei[EE + e0 + rl];
        int dhi = ei[EE + e0 + rh];
        float* plo = g_aggr + (size_t)dlo * 64 + 2 * tig;
        float* phi = g_aggr + (size_t)dhi * 64 + 2 * tig;
        RED_NT(0, A0); RED_NT(1, A1); RED_NT(2, A2); RED_NT(3, A3);
        RED_NT(4, A4); RED_NT(5, A5); RED_NT(6, A6); RED_NT(7, A7);
    }
}

// ---------------- per-node: root + bias + relu + BN + GRU (coalesced weights) ----
__global__ void k_node(int l, const float* __restrict__ root_w,
                       const float* __restrict__ conv_b, const float* __restrict__ bn,
                       const float* __restrict__ bih, const float* __restrict__ bhh) {
    __shared__ float hrow[64], mrow[64];
    const float* __restrict__ gT = g_gruT + l * (64 * 384);
    int n = blockIdx.x, o = threadIdx.x;
    float hv = g_h[n * 64 + o];
    hrow[o] = hv;
    __syncthreads();
    float acc = g_aggr[n * 64 + o] + conv_b[o];
    g_aggr[n * 64 + o] = 0.f;     // fused zero for next aggregation
#pragma unroll 16
    for (int i = 0; i < 64; i++) acc += hrow[i] * root_w[i * 64 + o];
    acc = fmaxf(acc, 0.f);
    acc = (acc - bn[128 + o]) * rsqrtf(bn[192 + o] + BN_EPS) * bn[o] + bn[64 + o];
    mrow[o] = acc;
    __syncthreads();
    float gir = bih[o], giz = bih[64 + o], gin = bih[128 + o];
    float ghr = bhh[o], ghz = bhh[64 + o], ghn = bhh[128 + o];
#pragma unroll 8
    for (int i = 0; i < 64; i++) {
        float mi = mrow[i], hi = hrow[i];
        const float* gi = gT + i * 384;
        gir += mi * gi[o];
        giz += mi * gi[64 + o];
        gin += mi * gi[128 + o];
        ghr += hi * gi[192 + o];
        ghz += hi * gi[256 + o];
        ghn += hi * gi[320 + o];
    }
    float r = 1.f / (1.f + expf(-(gir + ghr)));
    float z = 1.f / (1.f + expf(-(giz + ghz)));
    float nv = tanhf(gin + r * ghn);
    g_h[n * 64 + o] = (1.f - z) * nv + z * hv;
}

// ---------------- GraphConv scatter (vectorized red.v2) + fused pooled zero -------
__global__ void k_gcsc(const int* __restrict__ ei) {
    int idx = blockIdx.x * blockDim.x + threadIdx.x;   // E*32
    int e = idx >> 5, q = idx & 31;
    int s = ei[e], d = ei[EE + e];
    float2 v = *(const float2*)(g_h + (size_t)s * 64 + q * 2);
    asm volatile("red.global.add.v2.f32 [%0], {%1,%2};"
                 :: "l"(g_aggr + (size_t)d * 64 + q * 2), "f"(v.x), "f"(v.y) : "memory");
    if (idx < GG * DD) g_pooled[idx] = 0.f;
}

// ---------------- GraphConv linear + BN + pool scatter ----------------
__global__ void k_gconv(const float* __restrict__ relb, const float* __restrict__ bnl,
                        const int* __restrict__ batch) {
    __shared__ float arow[64], hrow[64];
    int n = blockIdx.x, o = threadIdx.x;
    arow[o] = g_aggr[n * 64 + o];
    hrow[o] = g_h[n * 64 + o];
    __syncthreads();
    float a = relb[o];
#pragma unroll 16
    for (int i = 0; i < 64; i++)
        a += arow[i] * g_gcT[i * 64 + o] + hrow[i] * g_gcT[4096 + i * 64 + o];
    a = fmaxf(a, 0.f);
    a = (a - bnl[128 + o]) * rsqrtf(bnl[192 + o] + BN_EPS) * bnl[o] + bnl[64 + o];
    atomicAdd(&g_pooled[batch[n] * 64 + o], a);
}

// ---------------- FC head ----------------
__global__ void k_head(const float* __restrict__ fc1_b, const float* __restrict__ fcbn1,
                       const float* __restrict__ fc2_b, const float* __restrict__ fcbn2,
                       const float* __restrict__ fcl_w, const float* __restrict__ fcl_b,
                       float* __restrict__ out) {
    __shared__ float prow[64], f1[256], f2[128], red[256];
    int g = blockIdx.x, t = threadIdx.x;
    if (t < 64) prow[t] = g_pooled[g * 64 + t];
    __syncthreads();
    {
        float a = fc1_b[t];
#pragma unroll 16
        for (int i = 0; i < 64; i++) a += prow[i] * g_fc1T[i * 256 + t];
        a = fmaxf(a, 0.f);
        a = (a - fcbn1[512 + t]) * rsqrtf(fcbn1[768 + t] + BN_EPS) * fcbn1[t] + fcbn1[256 + t];
        f1[t] = a;
    }
    __syncthreads();
    if (t < 128) {
        float a = fc2_b[t];
#pragma unroll 16
        for (int i = 0; i < 256; i++) a += f1[i] * g_fc2T[i * 128 + t];
        a = fmaxf(a, 0.f);
        a = (a - fcbn2[256 + t]) * rsqrtf(fcbn2[384 + t] + BN_EPS) * fcbn2[t] + fcbn2[128 + t];
        f2[t] = a;
    }
    __syncthreads();
    red[t] = (t < 128) ? f2[t] * fcl_w[t] : 0.f;
    __syncthreads();
    for (int s = 128; s > 0; s >>= 1) {
        if (t < s) red[t] += red[t + s];
        __syncthreads();
    }
    if (t == 0) out[g] = red[0] + fcl_b[0];
}

// ---------------- launcher ----------------
extern "C" void kernel_launch(void* const* d_in, const int* in_sizes, int n_in,
                              void* d_out, int out_size) {
    const float* x        = (const float*)d_in[0];
    const float* edge_attr= (const float*)d_in[1];
    const float* lin0_w   = (const float*)d_in[2];
    const float* lin0_b   = (const float*)d_in[3];
    const float* mlp1_w   = (const float*)d_in[4];
    const float* mlp1_b   = (const float*)d_in[5];
    const float* mlp2_w   = (const float*)d_in[6];
    const float* mlp2_b   = (const float*)d_in[7];
    const float* root_w   = (const float*)d_in[8];
    const float* conv_b   = (const float*)d_in[9];
    const float* bn       = (const float*)d_in[10];
    const float* gru_wih  = (const float*)d_in[11];
    const float* gru_whh  = (const float*)d_in[12];
    const float* gru_bih  = (const float*)d_in[13];
    const float* gru_bhh  = (const float*)d_in[14];
    const float* gc_rel_w = (const float*)d_in[15];
    const float* gc_rel_b = (const float*)d_in[16];
    const float* gc_root_w= (const float*)d_in[17];
    const float* bnl      = (const float*)d_in[18];
    const float* fc1_w    = (const float*)d_in[19];
    const float* fc1_b    = (const float*)d_in[20];
    const float* fcbn1    = (const float*)d_in[21];
    const float* fc2_w    = (const float*)d_in[22];
    const float* fc2_b    = (const float*)d_in[23];
    const float* fcbn2    = (const float*)d_in[24];
    const float* fcl_w    = (const float*)d_in[25];
    const float* fcl_b    = (const float*)d_in[26];
    const int*   ei       = (const int*)d_in[27];
    const int*   batch    = (const int*)d_in[28];
    float* out = (float*)d_out;

    cudaFuncSetAttribute(k_msg_mma, cudaFuncAttributeMaxDynamicSharedMemorySize, MSG_SMEM);

    k_perm<<<2496, 256>>>(mlp2_w, mlp2_b, gru_wih, gru_whh,
                          gc_rel_w, gc_root_w, fc1_w, fc2_w);                 // 0
    k_lin0<<<(NN * DD) / 256, 256>>>(x, lin0_w, lin0_b);                      // 1 (+aggr zero)
    k_msg_mma<<<EE / MT, 256, MSG_SMEM>>>(0, ei, mlp1_w, mlp1_b, edge_attr);  // 2
    k_node<<<NN, 64>>>(0, root_w, conv_b, bn, gru_bih, gru_bhh);              // 3 <- captured
    k_msg_mma<<<EE / MT, 256, MSG_SMEM>>>(1, ei, mlp1_w, mlp1_b, edge_attr);  // 4
    k_node<<<NN, 64>>>(1, root_w + 4096, conv_b + 64, bn + 256,
                       gru_bih + 192, gru_bhh + 192);                         // 5 (+aggr zero)
    k_gcsc<<<(EE * 32) / 256, 256>>>(ei);                                     // 6 (+pooled zero)
    k_gconv<<<NN, 64>>>(gc_rel_b, bnl, batch);                                // 7
    k_head<<<GG, 256>>>(fc1_b, fcbn1, fc2_b, fcbn2, fcl_w, fcl_b, out);       // 8
}